// round 5
// baseline (speedup 1.0000x reference)
#include <cuda_runtime.h>
#include <cuda_bf16.h>
#include <cstdint>

// Problem dims
#define N_LINK 2000
#define N_FLOW 30000
#define N_PATH 50000
#define E1 120000
#define E2 120000
#define HID 256
#define NH 4
#define HD 256      // per-head dim
#define HDTOT 1024  // NH*HD

// ---------------- scratch (static device arrays; no runtime alloc) ------------
__device__ float g_hlink[N_LINK * HID];
__device__ float g_hflow[N_FLOW * HID];
__device__ float g_hp0[N_PATH * HID];
__device__ float g_hp1[N_PATH * HID];   // h_path after conv1 == x_res1
__device__ float g_hp2[N_PATH * HID];   // h_path after conv2 == x_res2
__device__ float g_z[N_FLOW * HDTOT];   // z_src scratch (covers both convs)
__device__ float g_aggm[N_PATH * HID];  // head-meaned aggregation
__device__ float g_x1[N_PATH * HID];    // decoder hidden
__device__ float g_vl[HID * NH];
__device__ float g_vr[HID * NH];
__device__ float g_ce[NH];
__device__ float g_el[N_FLOW * NH];
__device__ float g_er[N_PATH * NH];
__device__ float g_elog[E1 * NH];       // edge logits -> exp numerators
__device__ unsigned g_maxenc[N_PATH * NH];
__device__ float g_denom[N_PATH * NH];

// order-preserving float<->uint for atomicMax
__device__ __forceinline__ unsigned fenc(float x) {
    unsigned b = __float_as_uint(x);
    return (b & 0x80000000u) ? ~b : (b | 0x80000000u);
}
__device__ __forceinline__ float fdec(unsigned u) {
    unsigned b = (u & 0x80000000u) ? (u & 0x7FFFFFFFu) : ~u;
    return __uint_as_float(b);
}
#define ENC_NEG_INF 0x007FFFFFu  // fenc(-inf)

// ---------------- small kernels ----------------------------------------------

template <int K>
__global__ void proj_kernel(const float* __restrict__ x, const float* __restrict__ W,
                            const float* __restrict__ b, float* __restrict__ out, int N) {
    __shared__ float xs[K];
    int n = blockIdx.x;
    if (n >= N) return;
    int j = threadIdx.x;
    if (j < K) xs[j] = x[n * K + j];
    __syncthreads();
    float acc = b[j];
#pragma unroll
    for (int k = 0; k < K; k++) acc = fmaf(xs[k], W[k * HID + j], acc);
    out[n * HID + j] = fmaxf(acc, 0.0f);
}

// v[k*NH+h] = sum_d fc[k*1024 + h*256 + d] * attn[h*256 + d]
__global__ void attnvec_kernel(const float* __restrict__ fc, const float* __restrict__ attn,
                               float* __restrict__ v) {
    int k = blockIdx.x;
    int h = threadIdx.x >> 5;
    int lane = threadIdx.x & 31;
    float s = 0.f;
    const float* fr = fc + (size_t)k * HDTOT + h * HD;
    const float* ar = attn + h * HD;
    for (int d = lane; d < HD; d += 32) s = fmaf(fr[d], ar[d], s);
#pragma unroll
    for (int o = 16; o; o >>= 1) s += __shfl_xor_sync(0xffffffffu, s, o);
    if (lane == 0) v[k * NH + h] = s;
}

// out[n*NH+h] = h_src[n,:] @ v[:,h]
__global__ void dotvec_kernel(const float* __restrict__ hsrc, const float* __restrict__ v,
                              float* __restrict__ out, int N) {
    int n = blockIdx.x;
    if (n >= N) return;
    int h = threadIdx.x >> 5;
    int lane = threadIdx.x & 31;
    const float* hr = hsrc + (size_t)n * HID;
    float s = 0.f;
    for (int k = lane; k < HID; k += 32) s = fmaf(hr[k], v[k * NH + h], s);
#pragma unroll
    for (int o = 16; o; o >>= 1) s += __shfl_xor_sync(0xffffffffu, s, o);
    if (lane == 0) out[n * NH + h] = s;
}

__global__ void init_seg_kernel(unsigned* __restrict__ maxenc, float* __restrict__ denom, int n) {
    int i = blockIdx.x * blockDim.x + threadIdx.x;
    if (i < n) { maxenc[i] = ENC_NEG_INF; denom[i] = 0.f; }
}

// pass A: edge logits (leaky-relu) + segment max
__global__ void edge_logits_kernel(const int* __restrict__ src, const int* __restrict__ dst,
                                   const float* __restrict__ el, const float* __restrict__ er,
                                   const float* __restrict__ e2p, const float* __restrict__ ce,
                                   float* __restrict__ elog, unsigned* __restrict__ maxenc,
                                   int E, int use_ee) {
    int i = blockIdx.x * blockDim.x + threadIdx.x;
    if (i >= E * NH) return;
    int e = i >> 2, h = i & 3;
    int s = src[e], t = dst[e];
    float v = el[s * NH + h] + er[t * NH + h];
    if (use_ee) v = fmaf(e2p[e], ce[h], v);
    v = (v > 0.f) ? v : 0.2f * v;
    elog[i] = v;
    atomicMax(&maxenc[t * NH + h], fenc(v));
}

// pass B: numerator exp + segment sum
__global__ void edge_exp_kernel(const int* __restrict__ dst, float* __restrict__ elog,
                                const unsigned* __restrict__ maxenc, float* __restrict__ denom,
                                int E) {
    int i = blockIdx.x * blockDim.x + threadIdx.x;
    if (i >= E * NH) return;
    int e = i >> 2, h = i & 3;
    int t = dst[e];
    float m = fdec(maxenc[t * NH + h]);
    float a = expf(elog[i] - m);
    elog[i] = a;
    atomicAdd(&denom[t * NH + h], a);
}

// pass C: aggregate (head mean fused), 4 edges per 256-thread block,
// 64 threads per edge, each thread handles 4 consecutive d via one red.v4.f32
__global__ void aggregate_kernel(const int* __restrict__ src, const int* __restrict__ dst,
                                 const float* __restrict__ anum, const float* __restrict__ denom,
                                 const float* __restrict__ z, float* __restrict__ aggm, int E) {
    __shared__ float al[4][NH];
    __shared__ int sidx[4], tidx[4];
    int e0 = blockIdx.x * 4;
    int tid = threadIdx.x;
    if (tid < 16) {
        int le = tid >> 2, h = tid & 3;
        int e = e0 + le;
        if (e < E) {
            int t = dst[e];
            float dn = denom[t * NH + h];
            al[le][h] = anum[e * NH + h] / fmaxf(dn, 1e-9f) * 0.25f;
            if (h == 0) { sidx[le] = src[e]; tidx[le] = t; }
        }
    }
    __syncthreads();
    int le = tid >> 6, t64 = tid & 63;
    int e = e0 + le;
    if (e >= E) return;
    int s = sidx[le], t = tidx[le];
    const float4* zr = (const float4*)(z + (size_t)s * HDTOT);
    float4 v = make_float4(0.f, 0.f, 0.f, 0.f);
#pragma unroll
    for (int h = 0; h < NH; h++) {
        float a = al[le][h];
        float4 zv = zr[h * 64 + t64];
        v.x = fmaf(a, zv.x, v.x);
        v.y = fmaf(a, zv.y, v.y);
        v.z = fmaf(a, zv.z, v.z);
        v.w = fmaf(a, zv.w, v.w);
    }
    float* p = aggm + (size_t)t * HID + t64 * 4;
    asm volatile("red.global.add.v4.f32 [%0], {%1,%2,%3,%4};"
                 :: "l"(p), "f"(v.x), "f"(v.y), "f"(v.z), "f"(v.w) : "memory");
}

// ---------------- 3xTF32 tensor-core GEMM (pre-split shared, reg prefetch) ----
// C[M,N] = op( concat_k(A0|A1|A2)[M, nseg*256] @ B[nseg*256, N] (+addv) (+bias), relu? )
// A segments all have leading dim 256 (row-major). B row-major leading dim N.
#define FLAG_RELU 1

__device__ __forceinline__ void split_tf32(float x, float& hi, float& lo) {
    uint32_t h;
    asm("cvt.rna.tf32.f32 %0, %1;" : "=r"(h) : "f"(x));
    hi = __uint_as_float(h);
    float r = x - hi;
    uint32_t l;
    asm("cvt.rna.tf32.f32 %0, %1;" : "=r"(l) : "f"(r));
    lo = __uint_as_float(l);
}

__device__ __forceinline__ void mma_tf32(float* c, const uint32_t* a, const uint32_t* b) {
    asm volatile(
        "mma.sync.aligned.m16n8k8.row.col.f32.tf32.tf32.f32 "
        "{%0,%1,%2,%3}, {%4,%5,%6,%7}, {%8,%9}, {%0,%1,%2,%3};"
        : "+f"(c[0]), "+f"(c[1]), "+f"(c[2]), "+f"(c[3])
        : "r"(a[0]), "r"(a[1]), "r"(a[2]), "r"(a[3]), "r"(b[0]), "r"(b[1]));
}

// Shared layouts (float2 = (tf32_hi, tf32_lo)):
//  As[m][k]: m=0..127, k=0..15, row stride 20 float2  (stride%16==4 -> conflict-free frags)
//  Bs[k][n]: k=0..15, n=0..127, row stride 132 float2 (stride%16==4 -> conflict-free frags)
#define AS_STRIDE 20
#define BS_STRIDE 132

__global__ __launch_bounds__(256) void gemm_tf32(
    const float* __restrict__ A0, const float* __restrict__ A1p, const float* __restrict__ A2p,
    const float* __restrict__ B, float* __restrict__ C,
    int M, int N, int nseg,
    const float* __restrict__ addv, const float* __restrict__ bias, int flags) {
    __shared__ float2 As[128 * AS_STRIDE];
    __shared__ float2 Bs[16 * BS_STRIDE];

    int bm = blockIdx.y * 128, bn = blockIdx.x * 128;
    int tid = threadIdx.x;
    int w = tid >> 5, lane = tid & 31;
    int gid = lane >> 2, tig = lane & 3;
    int wm = (w >> 2) * 64, wn = (w & 3) * 32;  // warp tile 64x32, warps 2x4

    // loader indices
    int a_row = tid >> 2, a_qc = (tid & 3) * 4;       // A: 64 rows per 256 threads, x2 iters
    int b_row = tid >> 5, b_nc = (tid & 31) * 4;      // B: 8 rows per 256 threads, x2 iters

    float acc[4][4][4];
#pragma unroll
    for (int i = 0; i < 4; i++)
#pragma unroll
        for (int j = 0; j < 4; j++)
#pragma unroll
            for (int q = 0; q < 4; q++) acc[i][j][q] = 0.f;

    int Ktot = nseg << 8;
    int ntile = Ktot >> 4;

    float4 arv[2], brv[2];
    // prefetch tile 0
    {
        const float* A = A0;
#pragma unroll
        for (int it = 0; it < 2; it++) {
            int row = a_row + it * 64;
            int gr = bm + row;
            arv[it] = (gr < M) ? *(const float4*)(A + (size_t)gr * 256 + a_qc)
                               : make_float4(0.f, 0.f, 0.f, 0.f);
            brv[it] = *(const float4*)(B + (size_t)(b_row + it * 8) * N + bn + b_nc);
        }
    }

    for (int t = 0; t < ntile; t++) {
        // split + store current tile to shared
#pragma unroll
        for (int it = 0; it < 2; it++) {
            int row = a_row + it * 64;
            float4 v = arv[it];
            float2 p;
            split_tf32(v.x, p.x, p.y); As[row * AS_STRIDE + a_qc + 0] = p;
            split_tf32(v.y, p.x, p.y); As[row * AS_STRIDE + a_qc + 1] = p;
            split_tf32(v.z, p.x, p.y); As[row * AS_STRIDE + a_qc + 2] = p;
            split_tf32(v.w, p.x, p.y); As[row * AS_STRIDE + a_qc + 3] = p;
            int brow = b_row + it * 8;
            v = brv[it];
            split_tf32(v.x, p.x, p.y); Bs[brow * BS_STRIDE + b_nc + 0] = p;
            split_tf32(v.y, p.x, p.y); Bs[brow * BS_STRIDE + b_nc + 1] = p;
            split_tf32(v.z, p.x, p.y); Bs[brow * BS_STRIDE + b_nc + 2] = p;
            split_tf32(v.w, p.x, p.y); Bs[brow * BS_STRIDE + b_nc + 3] = p;
        }
        __syncthreads();

        // prefetch next tile into registers (overlaps with MMA below)
        if (t + 1 < ntile) {
            int k0 = (t + 1) << 4;
            const float* A = (k0 < 256) ? A0 : (k0 < 512 ? A1p : A2p);
            int kk = k0 & 255;
#pragma unroll
            for (int it = 0; it < 2; it++) {
                int row = a_row + it * 64;
                int gr = bm + row;
                arv[it] = (gr < M) ? *(const float4*)(A + (size_t)gr * 256 + kk + a_qc)
                                   : make_float4(0.f, 0.f, 0.f, 0.f);
                brv[it] = *(const float4*)(B + (size_t)(k0 + b_row + it * 8) * N + bn + b_nc);
            }
        }

        // compute: two k=8 steps
#pragma unroll
        for (int ks = 0; ks < 16; ks += 8) {
            uint32_t bhi[4][2], blo[4][2];
#pragma unroll
            for (int j = 0; j < 4; j++) {
                int c0 = wn + 8 * j + gid;
                float2 u0 = Bs[(ks + tig) * BS_STRIDE + c0];
                float2 u1 = Bs[(ks + tig + 4) * BS_STRIDE + c0];
                bhi[j][0] = __float_as_uint(u0.x); blo[j][0] = __float_as_uint(u0.y);
                bhi[j][1] = __float_as_uint(u1.x); blo[j][1] = __float_as_uint(u1.y);
            }
#pragma unroll
            for (int i = 0; i < 4; i++) {
                int r0 = wm + 16 * i + gid;
                uint32_t ahi[4], alo[4];
                float2 v0 = As[r0 * AS_STRIDE + ks + tig];
                float2 v1 = As[(r0 + 8) * AS_STRIDE + ks + tig];
                float2 v2 = As[r0 * AS_STRIDE + ks + tig + 4];
                float2 v3 = As[(r0 + 8) * AS_STRIDE + ks + tig + 4];
                ahi[0] = __float_as_uint(v0.x); alo[0] = __float_as_uint(v0.y);
                ahi[1] = __float_as_uint(v1.x); alo[1] = __float_as_uint(v1.y);
                ahi[2] = __float_as_uint(v2.x); alo[2] = __float_as_uint(v2.y);
                ahi[3] = __float_as_uint(v3.x); alo[3] = __float_as_uint(v3.y);
#pragma unroll
                for (int j = 0; j < 4; j++) {
                    mma_tf32(acc[i][j], ahi, bhi[j]);
                    mma_tf32(acc[i][j], ahi, blo[j]);
                    mma_tf32(acc[i][j], alo, bhi[j]);
                }
            }
        }
        __syncthreads();
    }

    // epilogue
#pragma unroll
    for (int i = 0; i < 4; i++) {
#pragma unroll
        for (int j = 0; j < 4; j++) {
            int r0 = bm + wm + 16 * i + gid;
            int r1 = r0 + 8;
            int c = bn + wn + 8 * j + 2 * tig;
            float2 v0 = make_float2(acc[i][j][0], acc[i][j][1]);
            float2 v1 = make_float2(acc[i][j][2], acc[i][j][3]);
            float bx = 0.f, by = 0.f;
            if (bias) { bx = bias[c]; by = bias[c + 1]; }
            if (r0 < M) {
                size_t idx = (size_t)r0 * N + c;
                if (addv) { v0.x += addv[idx]; v0.y += addv[idx + 1]; }
                v0.x += bx; v0.y += by;
                if (flags & FLAG_RELU) { v0.x = fmaxf(v0.x, 0.f); v0.y = fmaxf(v0.y, 0.f); }
                *(float2*)(C + idx) = v0;
            }
            if (r1 < M) {
                size_t idx = (size_t)r1 * N + c;
                if (addv) { v1.x += addv[idx]; v1.y += addv[idx + 1]; }
                v1.x += bx; v1.y += by;
                if (flags & FLAG_RELU) { v1.x = fmaxf(v1.x, 0.f); v1.y = fmaxf(v1.y, 0.f); }
                *(float2*)(C + idx) = v1;
            }
        }
    }
}

// final: out[n,0:2] = x1[n,:]@W2[256,2] + b2 ; warp per row
__global__ void final_kernel(const float* __restrict__ x1, const float* __restrict__ W2,
                             const float* __restrict__ b2, float* __restrict__ out, int N) {
    int warp = (blockIdx.x * blockDim.x + threadIdx.x) >> 5;
    int lane = threadIdx.x & 31;
    if (warp >= N) return;
    const float* xr = x1 + (size_t)warp * HID;
    float s0 = 0.f, s1 = 0.f;
    for (int k = lane; k < HID; k += 32) {
        float xv = xr[k];
        s0 = fmaf(xv, W2[k * 2 + 0], s0);
        s1 = fmaf(xv, W2[k * 2 + 1], s1);
    }
#pragma unroll
    for (int o = 16; o; o >>= 1) {
        s0 += __shfl_xor_sync(0xffffffffu, s0, o);
        s1 += __shfl_xor_sync(0xffffffffu, s1, o);
    }
    if (lane == 0) {
        out[warp * 2 + 0] = s0 + b2[0];
        out[warp * 2 + 1] = s1 + b2[1];
    }
}

// ---------------- host launcher ----------------------------------------------
static inline void* sym(const void* s) {
    void* p = nullptr;
    cudaGetSymbolAddress(&p, s);
    return p;
}

extern "C" void kernel_launch(void* const* d_in, const int* in_sizes, int n_in,
                              void* d_out, int out_size) {
    const float* x_link = (const float*)d_in[0];
    const float* x_flow = (const float*)d_in[1];
    const float* x_path = (const float*)d_in[2];
    const float* e2p = (const float*)d_in[3];
    const float* Wp_link = (const float*)d_in[4];
    const float* bp_link = (const float*)d_in[5];
    const float* Wp_flow = (const float*)d_in[6];
    const float* bp_flow = (const float*)d_in[7];
    const float* Wp_path = (const float*)d_in[8];
    const float* bp_path = (const float*)d_in[9];
    const float* fc_src1 = (const float*)d_in[10];
    const float* fc_dst1 = (const float*)d_in[11];
    const float* fc_e1 = (const float*)d_in[12];
    const float* attn_l1 = (const float*)d_in[13];
    const float* attn_r1 = (const float*)d_in[14];
    const float* attn_e1 = (const float*)d_in[15];
    const float* res_W1 = (const float*)d_in[16];
    const float* fc_src2 = (const float*)d_in[17];
    const float* fc_dst2 = (const float*)d_in[18];
    const float* attn_l2 = (const float*)d_in[19];
    const float* attn_r2 = (const float*)d_in[20];
    const float* res_W2 = (const float*)d_in[21];
    const float* W1 = (const float*)d_in[22];
    const float* b1 = (const float*)d_in[23];
    const float* W2 = (const float*)d_in[24];
    const float* b2 = (const float*)d_in[25];
    const int* src1 = (const int*)d_in[26];
    const int* dst1 = (const int*)d_in[27];
    const int* src2 = (const int*)d_in[28];
    const int* dst2 = (const int*)d_in[29];
    float* out = (float*)d_out;

    float* hlink = (float*)sym(g_hlink);
    float* hflow = (float*)sym(g_hflow);
    float* hp0 = (float*)sym(g_hp0);
    float* hp1 = (float*)sym(g_hp1);
    float* hp2 = (float*)sym(g_hp2);
    float* z = (float*)sym(g_z);
    float* aggm = (float*)sym(g_aggm);
    float* x1 = (float*)sym(g_x1);
    float* vl = (float*)sym(g_vl);
    float* vr = (float*)sym(g_vr);
    float* ce = (float*)sym(g_ce);
    float* el = (float*)sym(g_el);
    float* er = (float*)sym(g_er);
    float* elog = (float*)sym(g_elog);
    unsigned* maxenc = (unsigned*)sym(g_maxenc);
    float* denom = (float*)sym(g_denom);

    // 1) per-type projections
    proj_kernel<8><<<N_LINK, HID>>>(x_link, Wp_link, bp_link, hlink, N_LINK);
    proj_kernel<16><<<N_FLOW, HID>>>(x_flow, Wp_flow, bp_flow, hflow, N_FLOW);
    proj_kernel<8><<<N_PATH, HID>>>(x_path, Wp_path, bp_path, hp0, N_PATH);

    dim3 gz1(HDTOT / 128, (N_LINK + 127) / 128);
    dim3 gz2(HDTOT / 128, (N_FLOW + 127) / 128);
    dim3 gres(HID / 128, (N_PATH + 127) / 128);

    // ====================== conv1: link -> path ======================
    attnvec_kernel<<<HID, 128>>>(fc_src1, attn_l1, vl);
    attnvec_kernel<<<HID, 128>>>(fc_dst1, attn_r1, vr);
    attnvec_kernel<<<1, 128>>>(fc_e1, attn_e1, ce);

    gemm_tf32<<<gz1, 256>>>(hlink, nullptr, nullptr, fc_src1, z, N_LINK, HDTOT, 1,
                            nullptr, nullptr, 0);
    dotvec_kernel<<<N_LINK, 128>>>(hlink, vl, el, N_LINK);
    dotvec_kernel<<<N_PATH, 128>>>(hp0, vr, er, N_PATH);

    init_seg_kernel<<<(N_PATH * NH + 255) / 256, 256>>>(maxenc, denom, N_PATH * NH);
    cudaMemsetAsync(aggm, 0, (size_t)N_PATH * HID * sizeof(float));

    edge_logits_kernel<<<(E1 * NH + 255) / 256, 256>>>(src1, dst1, el, er, e2p, ce, elog, maxenc, E1, 1);
    edge_exp_kernel<<<(E1 * NH + 255) / 256, 256>>>(dst1, elog, maxenc, denom, E1);
    aggregate_kernel<<<(E1 + 3) / 4, 256>>>(src1, dst1, elog, denom, z, aggm, E1);

    // hp1 = relu(aggm + hp0 @ res_W1)
    gemm_tf32<<<gres, 256>>>(hp0, nullptr, nullptr, res_W1, hp1, N_PATH, HID, 1,
                             aggm, nullptr, FLAG_RELU);

    // ====================== conv2: flow -> path ======================
    attnvec_kernel<<<HID, 128>>>(fc_src2, attn_l2, vl);
    attnvec_kernel<<<HID, 128>>>(fc_dst2, attn_r2, vr);

    gemm_tf32<<<gz2, 256>>>(hflow, nullptr, nullptr, fc_src2, z, N_FLOW, HDTOT, 1,
                            nullptr, nullptr, 0);
    dotvec_kernel<<<N_FLOW, 128>>>(hflow, vl, el, N_FLOW);
    dotvec_kernel<<<N_PATH, 128>>>(hp1, vr, er, N_PATH);

    init_seg_kernel<<<(N_PATH * NH + 255) / 256, 256>>>(maxenc, denom, N_PATH * NH);
    cudaMemsetAsync(aggm, 0, (size_t)N_PATH * HID * sizeof(float));

    edge_logits_kernel<<<(E2 * NH + 255) / 256, 256>>>(src2, dst2, el, er, nullptr, ce, elog, maxenc, E2, 0);
    edge_exp_kernel<<<(E2 * NH + 255) / 256, 256>>>(dst2, elog, maxenc, denom, E2);
    aggregate_kernel<<<(E2 + 3) / 4, 256>>>(src2, dst2, elog, denom, z, aggm, E2);

    // hp2 = relu(aggm + hp1 @ res_W2)
    gemm_tf32<<<gres, 256>>>(hp1, nullptr, nullptr, res_W2, hp2, N_PATH, HID, 1,
                             aggm, nullptr, FLAG_RELU);

    // ====================== decoder ======================
    // x1 = relu(concat(hp2, hp1, hp2) @ W1 + b1) as ONE segmented K=768 GEMM
    gemm_tf32<<<gres, 256>>>(hp2, hp1, hp2, W1, x1, N_PATH, HID, 3,
                             nullptr, b1, FLAG_RELU);

    // out = x1 @ W2 + b2
    final_kernel<<<(N_PATH * 32 + 255) / 256, 256>>>(x1, W2, b2, out, N_PATH);
}

// round 7
// speedup vs baseline: 1.3581x; 1.3581x over previous
#include <cuda_runtime.h>
#include <cuda_bf16.h>
#include <cstdint>

// Problem dims
#define N_LINK 2000
#define N_FLOW 30000
#define N_PATH 50000
#define E1 120000
#define E2 120000
#define HID 256
#define NH 4
#define HD 256      // per-head dim
#define HDTOT 1024  // NH*HD

// ---------------- scratch (static device arrays; no runtime alloc) ------------
__device__ float g_hlink[N_LINK * HID];
__device__ float g_hflow[N_FLOW * HID];
__device__ float g_hp0[N_PATH * HID];
__device__ float g_hp1[N_PATH * HID];   // h_path after conv1 == x_res1
__device__ float g_hp2[N_PATH * HID];   // h_path after conv2 == x_res2
__device__ float g_z1[N_LINK * HDTOT];  // conv1 z_src
__device__ float g_z2[N_FLOW * HDTOT];  // conv2 z_src
__device__ float g_aggm[N_PATH * HID];  // head-meaned aggregation
__device__ float g_x1[N_PATH * HID];    // decoder hidden
__device__ float g_vl1[HID * NH];
__device__ float g_vr1[HID * NH];
__device__ float g_vl2[HID * NH];
__device__ float g_vr2[HID * NH];
__device__ float g_ce[NH];
__device__ float g_el[N_FLOW * NH];
__device__ float g_er[N_PATH * NH];
__device__ float g_elog[E1 * NH];       // edge logits -> exp numerators
__device__ unsigned g_maxenc[N_PATH * NH];
__device__ float g_denom[N_PATH * NH];

// order-preserving float<->uint for atomicMax
__device__ __forceinline__ unsigned fenc(float x) {
    unsigned b = __float_as_uint(x);
    return (b & 0x80000000u) ? ~b : (b | 0x80000000u);
}
__device__ __forceinline__ float fdec(unsigned u) {
    unsigned b = (u & 0x80000000u) ? (u & 0x7FFFFFFFu) : ~u;
    return __uint_as_float(b);
}
#define ENC_NEG_INF 0x007FFFFFu  // fenc(-inf)

// ---------------- small kernels ----------------------------------------------

template <int K>
__global__ void proj_kernel(const float* __restrict__ x, const float* __restrict__ W,
                            const float* __restrict__ b, float* __restrict__ out, int N) {
    __shared__ float xs[K];
    int n = blockIdx.x;
    if (n >= N) return;
    int j = threadIdx.x;
    if (j < K) xs[j] = x[n * K + j];
    __syncthreads();
    float acc = b[j];
#pragma unroll
    for (int k = 0; k < K; k++) acc = fmaf(xs[k], W[k * HID + j], acc);
    out[n * HID + j] = fmaxf(acc, 0.0f);
}

// v[k*NH+h] = sum_d fc[k*1024 + h*256 + d] * attn[h*256 + d]
__global__ void attnvec_kernel(const float* __restrict__ fc, const float* __restrict__ attn,
                               float* __restrict__ v) {
    int k = blockIdx.x;
    int h = threadIdx.x >> 5;
    int lane = threadIdx.x & 31;
    float s = 0.f;
    const float* fr = fc + (size_t)k * HDTOT + h * HD;
    const float* ar = attn + h * HD;
    for (int d = lane; d < HD; d += 32) s = fmaf(fr[d], ar[d], s);
#pragma unroll
    for (int o = 16; o; o >>= 1) s += __shfl_xor_sync(0xffffffffu, s, o);
    if (lane == 0) v[k * NH + h] = s;
}

// out[n*NH+h] = h_src[n,:] @ v[:,h]
__global__ void dotvec_kernel(const float* __restrict__ hsrc, const float* __restrict__ v,
                              float* __restrict__ out, int N) {
    int n = blockIdx.x;
    if (n >= N) return;
    int h = threadIdx.x >> 5;
    int lane = threadIdx.x & 31;
    const float* hr = hsrc + (size_t)n * HID;
    float s = 0.f;
    for (int k = lane; k < HID; k += 32) s = fmaf(hr[k], v[k * NH + h], s);
#pragma unroll
    for (int o = 16; o; o >>= 1) s += __shfl_xor_sync(0xffffffffu, s, o);
    if (lane == 0) out[n * NH + h] = s;
}

__global__ void init_seg_kernel(unsigned* __restrict__ maxenc, float* __restrict__ denom, int n) {
    int i = blockIdx.x * blockDim.x + threadIdx.x;
    if (i < n) { maxenc[i] = ENC_NEG_INF; denom[i] = 0.f; }
}

// pass A: edge logits (leaky-relu) + segment max
__global__ void edge_logits_kernel(const int* __restrict__ src, const int* __restrict__ dst,
                                   const float* __restrict__ el, const float* __restrict__ er,
                                   const float* __restrict__ e2p, const float* __restrict__ ce,
                                   float* __restrict__ elog, unsigned* __restrict__ maxenc,
                                   int E, int use_ee) {
    int i = blockIdx.x * blockDim.x + threadIdx.x;
    if (i >= E * NH) return;
    int e = i >> 2, h = i & 3;
    int s = src[e], t = dst[e];
    float v = el[s * NH + h] + er[t * NH + h];
    if (use_ee) v = fmaf(e2p[e], ce[h], v);
    v = (v > 0.f) ? v : 0.2f * v;
    elog[i] = v;
    atomicMax(&maxenc[t * NH + h], fenc(v));
}

// pass B: numerator exp + segment sum
__global__ void edge_exp_kernel(const int* __restrict__ dst, float* __restrict__ elog,
                                const unsigned* __restrict__ maxenc, float* __restrict__ denom,
                                int E) {
    int i = blockIdx.x * blockDim.x + threadIdx.x;
    if (i >= E * NH) return;
    int e = i >> 2, h = i & 3;
    int t = dst[e];
    float m = fdec(maxenc[t * NH + h]);
    float a = expf(elog[i] - m);
    elog[i] = a;
    atomicAdd(&denom[t * NH + h], a);
}

// pass C: aggregate (head mean fused), 4 edges per 256-thread block,
// 64 threads per edge, each thread handles 4 consecutive d via one red.v4.f32
__global__ void aggregate_kernel(const int* __restrict__ src, const int* __restrict__ dst,
                                 const float* __restrict__ anum, const float* __restrict__ denom,
                                 const float* __restrict__ z, float* __restrict__ aggm, int E) {
    __shared__ float al[4][NH];
    __shared__ int sidx[4], tidx[4];
    int e0 = blockIdx.x * 4;
    int tid = threadIdx.x;
    if (tid < 16) {
        int le = tid >> 2, h = tid & 3;
        int e = e0 + le;
        if (e < E) {
            int t = dst[e];
            float dn = denom[t * NH + h];
            al[le][h] = anum[e * NH + h] / fmaxf(dn, 1e-9f) * 0.25f;
            if (h == 0) { sidx[le] = src[e]; tidx[le] = t; }
        }
    }
    __syncthreads();
    int le = tid >> 6, t64 = tid & 63;
    int e = e0 + le;
    if (e >= E) return;
    int s = sidx[le], t = tidx[le];
    const float4* zr = (const float4*)(z + (size_t)s * HDTOT);
    float4 v = make_float4(0.f, 0.f, 0.f, 0.f);
#pragma unroll
    for (int h = 0; h < NH; h++) {
        float a = al[le][h];
        float4 zv = zr[h * 64 + t64];
        v.x = fmaf(a, zv.x, v.x);
        v.y = fmaf(a, zv.y, v.y);
        v.z = fmaf(a, zv.z, v.z);
        v.w = fmaf(a, zv.w, v.w);
    }
    float* p = aggm + (size_t)t * HID + t64 * 4;
    asm volatile("red.global.add.v4.f32 [%0], {%1,%2,%3,%4};"
                 :: "l"(p), "f"(v.x), "f"(v.y), "f"(v.z), "f"(v.w) : "memory");
}

// ---------------- dual-bf16 tensor-core GEMM (corrected cross terms) ----------
// C[M,N] = op( concat_k(A0|A1|A2)[M, nseg*256] @ B[nseg*256, N] (+addv) (+bias), relu? )
// Each fp32 x -> packed word w = (bf16(x-hi)<<16) | bf16(x) = (hi, lo).
// Per real k, two bf16 k16 mmas reconstruct hi*hi + lo_a*hi_b + hi_a*lo_b:
//   mma1: A=(hi_a,lo_a)=w        B=(hi_b,hi_b)=byte_perm(w,w,0x1010)
//   mma2: A=(hi_a,0)=w&0xFFFF    B=(lo_b,0)=w>>16
// Dropped term lo_a*lo_b ~2^-18 relative.
#define FLAG_RELU 1

__device__ __forceinline__ uint32_t pack_split(float x) {
    __nv_bfloat16 h = __float2bfloat16_rn(x);
    float r = x - __bfloat162float(h);
    __nv_bfloat16 l = __float2bfloat16_rn(r);
    return ((uint32_t)__bfloat16_as_ushort(l) << 16) | (uint32_t)__bfloat16_as_ushort(h);
}

__device__ __forceinline__ void mma_bf16(float* c, const uint32_t* a, const uint32_t* b) {
    asm volatile(
        "mma.sync.aligned.m16n8k16.row.col.f32.bf16.bf16.f32 "
        "{%0,%1,%2,%3}, {%4,%5,%6,%7}, {%8,%9}, {%0,%1,%2,%3};"
        : "+f"(c[0]), "+f"(c[1]), "+f"(c[2]), "+f"(c[3])
        : "r"(a[0]), "r"(a[1]), "r"(a[2]), "r"(a[3]), "r"(b[0]), "r"(b[1]));
}

// Shared layouts (one uint32 word per fp32 element):
//  As[m][k]: 128 x 16 words, row stride 20 (conflict-free fragment reads)
//  Bs[k][n]: 16 x 128 words, row stride 136
__global__ __launch_bounds__(256) void gemm_db16(
    const float* __restrict__ A0, const float* __restrict__ A1p, const float* __restrict__ A2p,
    const float* __restrict__ B, float* __restrict__ C,
    int M, int N, int nseg,
    const float* __restrict__ addv, const float* __restrict__ bias, int flags) {
    __shared__ uint32_t As[128][20];
    __shared__ uint32_t Bs[16][136];

    int bm = blockIdx.y * 128, bn = blockIdx.x * 128;
    int tid = threadIdx.x;
    int w = tid >> 5, lane = tid & 31;
    int gid = lane >> 2, tig = lane & 3;
    int wm = (w >> 2) * 64, wn = (w & 3) * 32;  // warp tile 64x32, warps 2x4

    float acc[4][4][4];
#pragma unroll
    for (int i = 0; i < 4; i++)
#pragma unroll
        for (int j = 0; j < 4; j++)
#pragma unroll
            for (int q = 0; q < 4; q++) acc[i][j][q] = 0.f;

    int Ktot = nseg << 8;
    for (int k0 = 0; k0 < Ktot; k0 += 16) {
        const float* A = (k0 < 256) ? A0 : (k0 < 512 ? A1p : A2p);
        int kk = k0 & 255;
        // load + split A tile 128x16
#pragma unroll
        for (int it = 0; it < 2; it++) {
            int idx = tid + it * 256;
            int row = idx >> 2, qc = (idx & 3) * 4;
            float4 v = make_float4(0.f, 0.f, 0.f, 0.f);
            int gr = bm + row;
            if (gr < M) v = *(const float4*)(A + (size_t)gr * 256 + kk + qc);
            uint4 p = make_uint4(pack_split(v.x), pack_split(v.y), pack_split(v.z), pack_split(v.w));
            *(uint4*)&As[row][qc] = p;
        }
        // load + split B tile 16x128
#pragma unroll
        for (int it = 0; it < 2; it++) {
            int idx = tid + it * 256;
            int row = idx >> 5, nc = (idx & 31) * 4;
            float4 v = *(const float4*)(B + (size_t)(k0 + row) * N + bn + nc);
            uint4 p = make_uint4(pack_split(v.x), pack_split(v.y), pack_split(v.z), pack_split(v.w));
            *(uint4*)&Bs[row][nc] = p;
        }
        __syncthreads();
#pragma unroll
        for (int ks = 0; ks < 16; ks += 8) {
            uint32_t b1r[4][2], b2r[4][2];
#pragma unroll
            for (int j = 0; j < 4; j++) {
                int c0 = wn + 8 * j + gid;
                uint32_t w0 = Bs[ks + tig][c0];
                uint32_t w1 = Bs[ks + tig + 4][c0];
                b1r[j][0] = __byte_perm(w0, w0, 0x1010);  // (hi,hi)
                b1r[j][1] = __byte_perm(w1, w1, 0x1010);
                b2r[j][0] = w0 >> 16;                     // (lo,0)
                b2r[j][1] = w1 >> 16;
            }
#pragma unroll
            for (int i = 0; i < 4; i++) {
                int r0 = wm + 16 * i + gid;
                uint32_t a1[4], a2[4];
                a1[0] = As[r0][ks + tig];
                a1[1] = As[r0 + 8][ks + tig];
                a1[2] = As[r0][ks + tig + 4];
                a1[3] = As[r0 + 8][ks + tig + 4];
#pragma unroll
                for (int q = 0; q < 4; q++) a2[q] = a1[q] & 0xFFFFu;  // (hi,0)
#pragma unroll
                for (int j = 0; j < 4; j++) {
                    mma_bf16(acc[i][j], a1, b1r[j]);  // hi*hi + lo_a*hi_b
                    mma_bf16(acc[i][j], a2, b2r[j]);  // hi_a*lo_b
                }
            }
        }
        __syncthreads();
    }

    // epilogue
#pragma unroll
    for (int i = 0; i < 4; i++) {
#pragma unroll
        for (int j = 0; j < 4; j++) {
            int r0 = bm + wm + 16 * i + gid;
            int r1 = r0 + 8;
            int c = bn + wn + 8 * j + 2 * tig;
            float2 v0 = make_float2(acc[i][j][0], acc[i][j][1]);
            float2 v1 = make_float2(acc[i][j][2], acc[i][j][3]);
            float bx = 0.f, by = 0.f;
            if (bias) { bx = bias[c]; by = bias[c + 1]; }
            if (r0 < M) {
                size_t idx = (size_t)r0 * N + c;
                if (addv) { v0.x += addv[idx]; v0.y += addv[idx + 1]; }
                v0.x += bx; v0.y += by;
                if (flags & FLAG_RELU) { v0.x = fmaxf(v0.x, 0.f); v0.y = fmaxf(v0.y, 0.f); }
                *(float2*)(C + idx) = v0;
            }
            if (r1 < M) {
                size_t idx = (size_t)r1 * N + c;
                if (addv) { v1.x += addv[idx]; v1.y += addv[idx + 1]; }
                v1.x += bx; v1.y += by;
                if (flags & FLAG_RELU) { v1.x = fmaxf(v1.x, 0.f); v1.y = fmaxf(v1.y, 0.f); }
                *(float2*)(C + idx) = v1;
            }
        }
    }
}

// final: out[n,0:2] = x1[n,:]@W2[256,2] + b2 ; warp per row
__global__ void final_kernel(const float* __restrict__ x1, const float* __restrict__ W2,
                             const float* __restrict__ b2, float* __restrict__ out, int N) {
    int warp = (blockIdx.x * blockDim.x + threadIdx.x) >> 5;
    int lane = threadIdx.x & 31;
    if (warp >= N) return;
    const float* xr = x1 + (size_t)warp * HID;
    float s0 = 0.f, s1 = 0.f;
    for (int k = lane; k < HID; k += 32) {
        float xv = xr[k];
        s0 = fmaf(xv, W2[k * 2 + 0], s0);
        s1 = fmaf(xv, W2[k * 2 + 1], s1);
    }
#pragma unroll
    for (int o = 16; o; o >>= 1) {
        s0 += __shfl_xor_sync(0xffffffffu, s0, o);
        s1 += __shfl_xor_sync(0xffffffffu, s1, o);
    }
    if (lane == 0) {
        out[warp * 2 + 0] = s0 + b2[0];
        out[warp * 2 + 1] = s1 + b2[1];
    }
}

// ---------------- host launcher ----------------------------------------------
static inline void* sym(const void* s) {
    void* p = nullptr;
    cudaGetSymbolAddress(&p, s);
    return p;
}

extern "C" void kernel_launch(void* const* d_in, const int* in_sizes, int n_in,
                              void* d_out, int out_size) {
    const float* x_link = (const float*)d_in[0];
    const float* x_flow = (const float*)d_in[1];
    const float* x_path = (const float*)d_in[2];
    const float* e2p = (const float*)d_in[3];
    const float* Wp_link = (const float*)d_in[4];
    const float* bp_link = (const float*)d_in[5];
    const float* Wp_flow = (const float*)d_in[6];
    const float* bp_flow = (const float*)d_in[7];
    const float* Wp_path = (const float*)d_in[8];
    const float* bp_path = (const float*)d_in[9];
    const float* fc_src1 = (const float*)d_in[10];
    const float* fc_dst1 = (const float*)d_in[11];
    const float* fc_e1 = (const float*)d_in[12];
    const float* attn_l1 = (const float*)d_in[13];
    const float* attn_r1 = (const float*)d_in[14];
    const float* attn_e1 = (const float*)d_in[15];
    const float* res_W1 = (const float*)d_in[16];
    const float* fc_src2 = (const float*)d_in[17];
    const float* fc_dst2 = (const float*)d_in[18];
    const float* attn_l2 = (const float*)d_in[19];
    const float* attn_r2 = (const float*)d_in[20];
    const float* res_W2 = (const float*)d_in[21];
    const float* W1 = (const float*)d_in[22];
    const float* b1 = (const float*)d_in[23];
    const float* W2 = (const float*)d_in[24];
    const float* b2 = (const float*)d_in[25];
    const int* src1 = (const int*)d_in[26];
    const int* dst1 = (const int*)d_in[27];
    const int* src2 = (const int*)d_in[28];
    const int* dst2 = (const int*)d_in[29];
    float* out = (float*)d_out;

    float* hlink = (float*)sym(g_hlink);
    float* hflow = (float*)sym(g_hflow);
    float* hp0 = (float*)sym(g_hp0);
    float* hp1 = (float*)sym(g_hp1);
    float* hp2 = (float*)sym(g_hp2);
    float* z1 = (float*)sym(g_z1);
    float* z2 = (float*)sym(g_z2);
    float* aggm = (float*)sym(g_aggm);
    float* x1 = (float*)sym(g_x1);
    float* vl1 = (float*)sym(g_vl1);
    float* vr1 = (float*)sym(g_vr1);
    float* vl2 = (float*)sym(g_vl2);
    float* vr2 = (float*)sym(g_vr2);
    float* ce = (float*)sym(g_ce);
    float* el = (float*)sym(g_el);
    float* er = (float*)sym(g_er);
    float* elog = (float*)sym(g_elog);
    unsigned* maxenc = (unsigned*)sym(g_maxenc);
    float* denom = (float*)sym(g_denom);

    dim3 gz1(HDTOT / 128, (N_LINK + 127) / 128);
    dim3 gz2(HDTOT / 128, (N_FLOW + 127) / 128);
    dim3 gres(HID / 128, (N_PATH + 127) / 128);

    // Launch order chosen so launch index 5 (ncu -s 5 -c 1) is the BIG GEMM (z2).
    proj_kernel<8><<<N_LINK, HID>>>(x_link, Wp_link, bp_link, hlink, N_LINK);       // 0
    proj_kernel<16><<<N_FLOW, HID>>>(x_flow, Wp_flow, bp_flow, hflow, N_FLOW);      // 1
    proj_kernel<8><<<N_PATH, HID>>>(x_path, Wp_path, bp_path, hp0, N_PATH);         // 2
    attnvec_kernel<<<HID, 128>>>(fc_src2, attn_l2, vl2);                            // 3
    attnvec_kernel<<<HID, 128>>>(fc_dst2, attn_r2, vr2);                            // 4
    gemm_db16<<<gz2, 256>>>(hflow, nullptr, nullptr, fc_src2, z2, N_FLOW, HDTOT, 1, // 5 <- profiled
                            nullptr, nullptr, 0);

    // ====================== conv1: link -> path ======================
    attnvec_kernel<<<HID, 128>>>(fc_src1, attn_l1, vl1);
    attnvec_kernel<<<HID, 128>>>(fc_dst1, attn_r1, vr1);
    attnvec_kernel<<<1, 128>>>(fc_e1, attn_e1, ce);

    gemm_db16<<<gz1, 256>>>(hlink, nullptr, nullptr, fc_src1, z1, N_LINK, HDTOT, 1,
                            nullptr, nullptr, 0);
    dotvec_kernel<<<N_LINK, 128>>>(hlink, vl1, el, N_LINK);
    dotvec_kernel<<<N_PATH, 128>>>(hp0, vr1, er, N_PATH);

    init_seg_kernel<<<(N_PATH * NH + 255) / 256, 256>>>(maxenc, denom, N_PATH * NH);
    cudaMemsetAsync(aggm, 0, (size_t)N_PATH * HID * sizeof(float));

    edge_logits_kernel<<<(E1 * NH + 255) / 256, 256>>>(src1, dst1, el, er, e2p, ce, elog, maxenc, E1, 1);
    edge_exp_kernel<<<(E1 * NH + 255) / 256, 256>>>(dst1, elog, maxenc, denom, E1);
    aggregate_kernel<<<(E1 + 3) / 4, 256>>>(src1, dst1, elog, denom, z1, aggm, E1);

    // hp1 = relu(aggm + hp0 @ res_W1)
    gemm_db16<<<gres, 256>>>(hp0, nullptr, nullptr, res_W1, hp1, N_PATH, HID, 1,
                             aggm, nullptr, FLAG_RELU);

    // ====================== conv2: flow -> path ======================
    dotvec_kernel<<<N_FLOW, 128>>>(hflow, vl2, el, N_FLOW);
    dotvec_kernel<<<N_PATH, 128>>>(hp1, vr2, er, N_PATH);

    init_seg_kernel<<<(N_PATH * NH + 255) / 256, 256>>>(maxenc, denom, N_PATH * NH);
    cudaMemsetAsync(aggm, 0, (size_t)N_PATH * HID * sizeof(float));

    edge_logits_kernel<<<(E2 * NH + 255) / 256, 256>>>(src2, dst2, el, er, nullptr, ce, elog, maxenc, E2, 0);
    edge_exp_kernel<<<(E2 * NH + 255) / 256, 256>>>(dst2, elog, maxenc, denom, E2);
    aggregate_kernel<<<(E2 + 3) / 4, 256>>>(src2, dst2, elog, denom, z2, aggm, E2);

    // hp2 = relu(aggm + hp1 @ res_W2)
    gemm_db16<<<gres, 256>>>(hp1, nullptr, nullptr, res_W2, hp2, N_PATH, HID, 1,
                             aggm, nullptr, FLAG_RELU);

    // ====================== decoder ======================
    // x1 = relu(concat(hp2, hp1, hp2) @ W1 + b1) as ONE segmented K=768 GEMM
    gemm_db16<<<gres, 256>>>(hp2, hp1, hp2, W1, x1, N_PATH, HID, 3,
                             nullptr, b1, FLAG_RELU);

    // out = x1 @ W2 + b2
    final_kernel<<<(N_PATH * 32 + 255) / 256, 256>>>(x1, W2, b2, out, N_PATH);
}

// round 8
// speedup vs baseline: 1.4070x; 1.0360x over previous
#include <cuda_runtime.h>
#include <cuda_bf16.h>
#include <cstdint>

// Problem dims
#define N_LINK 2000
#define N_FLOW 30000
#define N_PATH 50000
#define E1 120000
#define E2 120000
#define HID 256
#define NH 4
#define HD 256      // per-head dim
#define HDTOT 1024  // NH*HD

// ---------------- scratch (static device arrays; no runtime alloc) ------------
__device__ float g_hlink[N_LINK * HID];
__device__ float g_hflow[N_FLOW * HID];
__device__ float g_hp0[N_PATH * HID];
__device__ float g_hp1[N_PATH * HID];
__device__ float g_hp2[N_PATH * HID];
__device__ float g_z1[N_LINK * HDTOT];
__device__ float g_z2[N_FLOW * HDTOT];
__device__ float g_aggm[N_PATH * HID];
__device__ float g_x1[N_PATH * HID];
// packed (hi,lo) bf16-pair copies for GEMM operands
__device__ uint32_t g_hlinkp[N_LINK * HID];
__device__ uint32_t g_hflowp[N_FLOW * HID];
__device__ uint32_t g_hp0p[N_PATH * HID];
__device__ uint32_t g_hp1p[N_PATH * HID];
__device__ uint32_t g_hp2p[N_PATH * HID];
__device__ uint32_t g_fc1p[HID * HDTOT];
__device__ uint32_t g_fc2p[HID * HDTOT];
__device__ uint32_t g_rw1p[HID * HID];
__device__ uint32_t g_rw2p[HID * HID];
__device__ uint32_t g_w1p[3 * HID * HID];
// attention vectors / edge scratch
__device__ float g_vl1[HID * NH];
__device__ float g_vr1[HID * NH];
__device__ float g_vl2[HID * NH];
__device__ float g_vr2[HID * NH];
__device__ float g_ce[NH];
__device__ float g_el[N_FLOW * NH];
__device__ float g_er[N_PATH * NH];
__device__ float g_elog[E1 * NH];
__device__ float g_denom[N_PATH * NH];

// ---------------- packing helpers ---------------------------------------------
__device__ __forceinline__ uint32_t pack_split(float x) {
    __nv_bfloat16 h = __float2bfloat16_rn(x);
    float r = x - __bfloat162float(h);
    __nv_bfloat16 l = __float2bfloat16_rn(r);
    return ((uint32_t)__bfloat16_as_ushort(l) << 16) | (uint32_t)__bfloat16_as_ushort(h);
}

__global__ void pack_kernel(const float* __restrict__ in, uint32_t* __restrict__ out, int n) {
    int i = blockIdx.x * blockDim.x + threadIdx.x;
    if (i < n) out[i] = pack_split(in[i]);
}

// ---------------- small kernels ----------------------------------------------

template <int K>
__global__ void proj_kernel(const float* __restrict__ x, const float* __restrict__ W,
                            const float* __restrict__ b, float* __restrict__ out,
                            uint32_t* __restrict__ outp, int N) {
    __shared__ float xs[K];
    int n = blockIdx.x;
    if (n >= N) return;
    int j = threadIdx.x;
    if (j < K) xs[j] = x[n * K + j];
    __syncthreads();
    float acc = b[j];
#pragma unroll
    for (int k = 0; k < K; k++) acc = fmaf(xs[k], W[k * HID + j], acc);
    acc = fmaxf(acc, 0.0f);
    out[n * HID + j] = acc;
    outp[n * HID + j] = pack_split(acc);
}

// v[k*NH+h] = sum_d fc[k*1024 + h*256 + d] * attn[h*256 + d]
__global__ void attnvec_kernel(const float* __restrict__ fc, const float* __restrict__ attn,
                               float* __restrict__ v) {
    int k = blockIdx.x;
    int h = threadIdx.x >> 5;
    int lane = threadIdx.x & 31;
    float s = 0.f;
    const float* fr = fc + (size_t)k * HDTOT + h * HD;
    const float* ar = attn + h * HD;
    for (int d = lane; d < HD; d += 32) s = fmaf(fr[d], ar[d], s);
#pragma unroll
    for (int o = 16; o; o >>= 1) s += __shfl_xor_sync(0xffffffffu, s, o);
    if (lane == 0) v[k * NH + h] = s;
}

// out[n*NH+h] = h_src[n,:] @ v[:,h]
__global__ void dotvec_kernel(const float* __restrict__ hsrc, const float* __restrict__ v,
                              float* __restrict__ out, int N) {
    int n = blockIdx.x;
    if (n >= N) return;
    int h = threadIdx.x >> 5;
    int lane = threadIdx.x & 31;
    const float* hr = hsrc + (size_t)n * HID;
    float s = 0.f;
    for (int k = lane; k < HID; k += 32) s = fmaf(hr[k], v[k * NH + h], s);
#pragma unroll
    for (int o = 16; o; o >>= 1) s += __shfl_xor_sync(0xffffffffu, s, o);
    if (lane == 0) out[n * NH + h] = s;
}

// fused softmax numerator + denominator (max-shift dropped: logits are O(0.1),
// exp overflow impossible; alpha = a/denom is shift-invariant)
__global__ void edge_softmax_kernel(const int* __restrict__ src, const int* __restrict__ dst,
                                    const float* __restrict__ el, const float* __restrict__ er,
                                    const float* __restrict__ e2p, const float* __restrict__ ce,
                                    float* __restrict__ elog, float* __restrict__ denom,
                                    int E, int use_ee) {
    int i = blockIdx.x * blockDim.x + threadIdx.x;
    if (i >= E * NH) return;
    int e = i >> 2, h = i & 3;
    int s = src[e], t = dst[e];
    float v = el[s * NH + h] + er[t * NH + h];
    if (use_ee) v = fmaf(e2p[e], ce[h], v);
    v = (v > 0.f) ? v : 0.2f * v;
    float a = expf(v);
    elog[i] = a;
    atomicAdd(&denom[t * NH + h], a);
}

// aggregate (head mean fused), 4 edges per 256-thread block
__global__ void aggregate_kernel(const int* __restrict__ src, const int* __restrict__ dst,
                                 const float* __restrict__ anum, const float* __restrict__ denom,
                                 const float* __restrict__ z, float* __restrict__ aggm, int E) {
    __shared__ float al[4][NH];
    __shared__ int sidx[4], tidx[4];
    int e0 = blockIdx.x * 4;
    int tid = threadIdx.x;
    if (tid < 16) {
        int le = tid >> 2, h = tid & 3;
        int e = e0 + le;
        if (e < E) {
            int t = dst[e];
            float dn = denom[t * NH + h];
            al[le][h] = anum[e * NH + h] / fmaxf(dn, 1e-9f) * 0.25f;
            if (h == 0) { sidx[le] = src[e]; tidx[le] = t; }
        }
    }
    __syncthreads();
    int le = tid >> 6, t64 = tid & 63;
    int e = e0 + le;
    if (e >= E) return;
    int s = sidx[le], t = tidx[le];
    const float4* zr = (const float4*)(z + (size_t)s * HDTOT);
    float4 v = make_float4(0.f, 0.f, 0.f, 0.f);
#pragma unroll
    for (int h = 0; h < NH; h++) {
        float a = al[le][h];
        float4 zv = zr[h * 64 + t64];
        v.x = fmaf(a, zv.x, v.x);
        v.y = fmaf(a, zv.y, v.y);
        v.z = fmaf(a, zv.z, v.z);
        v.w = fmaf(a, zv.w, v.w);
    }
    float* p = aggm + (size_t)t * HID + t64 * 4;
    asm volatile("red.global.add.v4.f32 [%0], {%1,%2,%3,%4};"
                 :: "l"(p), "f"(v.x), "f"(v.y), "f"(v.z), "f"(v.w) : "memory");
}

// ---------------- dual-bf16 GEMM, pre-packed operands + cp.async 2-stage ------
// C = op( concat_k(A0|A1|A2)[M, nseg*256] @ B[nseg*256, N] (+addv) (+bias), relu? )
// Inputs are packed (hi,lo) words. Per real k, two bf16 k16 mmas give
// hi*hi + lo_a*hi_b + hi_a*lo_b (lo*lo ~2^-18 dropped).
#define FLAG_RELU 1
#define STAGES 2

__device__ __forceinline__ void mma_bf16(float* c, const uint32_t* a, const uint32_t* b) {
    asm volatile(
        "mma.sync.aligned.m16n8k16.row.col.f32.bf16.bf16.f32 "
        "{%0,%1,%2,%3}, {%4,%5,%6,%7}, {%8,%9}, {%0,%1,%2,%3};"
        : "+f"(c[0]), "+f"(c[1]), "+f"(c[2]), "+f"(c[3])
        : "r"(a[0]), "r"(a[1]), "r"(a[2]), "r"(a[3]), "r"(b[0]), "r"(b[1]));
}

__global__ __launch_bounds__(256) void gemm_db16(
    const uint32_t* __restrict__ A0, const uint32_t* __restrict__ A1p, const uint32_t* __restrict__ A2p,
    const uint32_t* __restrict__ B, float* __restrict__ C, uint32_t* __restrict__ Cp,
    int M, int N, int nseg,
    const float* __restrict__ addv, const float* __restrict__ bias, int flags) {
    __shared__ uint32_t As[STAGES][128][20];
    __shared__ uint32_t Bs[STAGES][16][136];

    int bm = blockIdx.y * 128, bn = blockIdx.x * 128;
    int tid = threadIdx.x;
    int w = tid >> 5, lane = tid & 31;
    int gid = lane >> 2, tig = lane & 3;
    int wm = (w >> 2) * 64, wn = (w & 3) * 32;  // warp tile 64x32, warps 2x4

    int Ktot = nseg << 8;
    int ntile = Ktot >> 4;

    // tile loader: issues 4 cp.async.cg (A:2, B:2) per thread
    auto load_tile = [&](int slot, int t) {
        int k0 = t << 4;
        const uint32_t* A = (k0 < 256) ? A0 : (k0 < 512 ? A1p : A2p);
        int kk = k0 & 255;
#pragma unroll
        for (int it = 0; it < 2; it++) {
            int idx = tid + it * 256;
            int row = idx >> 2, qc = (idx & 3) * 4;
            int gr = bm + row;
            int grc = gr < M ? gr : 0;
            const uint32_t* g = A + (size_t)grc * 256 + kk + qc;
            uint32_t sa = (uint32_t)__cvta_generic_to_shared(&As[slot][row][qc]);
            asm volatile("cp.async.cg.shared.global [%0], [%1], 16, %2;"
                         :: "r"(sa), "l"(g), "r"(gr < M ? 16 : 0) : "memory");
            int brow = idx >> 5, nc = (idx & 31) * 4;
            const uint32_t* gB = B + (size_t)(k0 + brow) * N + bn + nc;
            uint32_t sb = (uint32_t)__cvta_generic_to_shared(&Bs[slot][brow][nc]);
            asm volatile("cp.async.cg.shared.global [%0], [%1], 16, 16;"
                         :: "r"(sb), "l"(gB) : "memory");
        }
    };

    float acc[4][4][4];
#pragma unroll
    for (int i = 0; i < 4; i++)
#pragma unroll
        for (int j = 0; j < 4; j++)
#pragma unroll
            for (int q = 0; q < 4; q++) acc[i][j][q] = 0.f;

    // prologue
    load_tile(0, 0);
    asm volatile("cp.async.commit_group;" ::: "memory");

    for (int t = 0; t < ntile; t++) {
        asm volatile("cp.async.wait_group 0;" ::: "memory");
        __syncthreads();
        int nt = t + 1;
        if (nt < ntile) {
            load_tile(nt & 1, nt);
            asm volatile("cp.async.commit_group;" ::: "memory");
        }
        int sl = t & 1;
#pragma unroll
        for (int ks = 0; ks < 16; ks += 8) {
            uint32_t b1r[4][2], b2r[4][2];
#pragma unroll
            for (int j = 0; j < 4; j++) {
                int c0 = wn + 8 * j + gid;
                uint32_t w0 = Bs[sl][ks + tig][c0];
                uint32_t w1 = Bs[sl][ks + tig + 4][c0];
                b1r[j][0] = __byte_perm(w0, w0, 0x1010);  // (hi,hi)
                b1r[j][1] = __byte_perm(w1, w1, 0x1010);
                b2r[j][0] = w0 >> 16;                     // (lo,0)
                b2r[j][1] = w1 >> 16;
            }
#pragma unroll
            for (int i = 0; i < 4; i++) {
                int r0 = wm + 16 * i + gid;
                uint32_t a1[4], a2[4];
                a1[0] = As[sl][r0][ks + tig];
                a1[1] = As[sl][r0 + 8][ks + tig];
                a1[2] = As[sl][r0][ks + tig + 4];
                a1[3] = As[sl][r0 + 8][ks + tig + 4];
#pragma unroll
                for (int q = 0; q < 4; q++) a2[q] = a1[q] & 0xFFFFu;  // (hi,0)
#pragma unroll
                for (int j = 0; j < 4; j++) {
                    mma_bf16(acc[i][j], a1, b1r[j]);  // hi*hi + lo_a*hi_b
                    mma_bf16(acc[i][j], a2, b2r[j]);  // hi_a*lo_b
                }
            }
        }
        __syncthreads();
    }

    // epilogue
#pragma unroll
    for (int i = 0; i < 4; i++) {
#pragma unroll
        for (int j = 0; j < 4; j++) {
            int r0 = bm + wm + 16 * i + gid;
            int r1 = r0 + 8;
            int c = bn + wn + 8 * j + 2 * tig;
            float2 v0 = make_float2(acc[i][j][0], acc[i][j][1]);
            float2 v1 = make_float2(acc[i][j][2], acc[i][j][3]);
            float bx = 0.f, by = 0.f;
            if (bias) { bx = bias[c]; by = bias[c + 1]; }
            if (r0 < M) {
                size_t idx = (size_t)r0 * N + c;
                if (addv) { v0.x += addv[idx]; v0.y += addv[idx + 1]; }
                v0.x += bx; v0.y += by;
                if (flags & FLAG_RELU) { v0.x = fmaxf(v0.x, 0.f); v0.y = fmaxf(v0.y, 0.f); }
                *(float2*)(C + idx) = v0;
                if (Cp) { Cp[idx] = pack_split(v0.x); Cp[idx + 1] = pack_split(v0.y); }
            }
            if (r1 < M) {
                size_t idx = (size_t)r1 * N + c;
                if (addv) { v1.x += addv[idx]; v1.y += addv[idx + 1]; }
                v1.x += bx; v1.y += by;
                if (flags & FLAG_RELU) { v1.x = fmaxf(v1.x, 0.f); v1.y = fmaxf(v1.y, 0.f); }
                *(float2*)(C + idx) = v1;
                if (Cp) { Cp[idx] = pack_split(v1.x); Cp[idx + 1] = pack_split(v1.y); }
            }
        }
    }
}

// final: out[n,0:2] = x1[n,:]@W2[256,2] + b2 ; warp per row
__global__ void final_kernel(const float* __restrict__ x1, const float* __restrict__ W2,
                             const float* __restrict__ b2, float* __restrict__ out, int N) {
    int warp = (blockIdx.x * blockDim.x + threadIdx.x) >> 5;
    int lane = threadIdx.x & 31;
    if (warp >= N) return;
    const float* xr = x1 + (size_t)warp * HID;
    float s0 = 0.f, s1 = 0.f;
    for (int k = lane; k < HID; k += 32) {
        float xv = xr[k];
        s0 = fmaf(xv, W2[k * 2 + 0], s0);
        s1 = fmaf(xv, W2[k * 2 + 1], s1);
    }
#pragma unroll
    for (int o = 16; o; o >>= 1) {
        s0 += __shfl_xor_sync(0xffffffffu, s0, o);
        s1 += __shfl_xor_sync(0xffffffffu, s1, o);
    }
    if (lane == 0) {
        out[warp * 2 + 0] = s0 + b2[0];
        out[warp * 2 + 1] = s1 + b2[1];
    }
}

// ---------------- host launcher ----------------------------------------------
static inline void* sym(const void* s) {
    void* p = nullptr;
    cudaGetSymbolAddress(&p, s);
    return p;
}

extern "C" void kernel_launch(void* const* d_in, const int* in_sizes, int n_in,
                              void* d_out, int out_size) {
    const float* x_link = (const float*)d_in[0];
    const float* x_flow = (const float*)d_in[1];
    const float* x_path = (const float*)d_in[2];
    const float* e2p = (const float*)d_in[3];
    const float* Wp_link = (const float*)d_in[4];
    const float* bp_link = (const float*)d_in[5];
    const float* Wp_flow = (const float*)d_in[6];
    const float* bp_flow = (const float*)d_in[7];
    const float* Wp_path = (const float*)d_in[8];
    const float* bp_path = (const float*)d_in[9];
    const float* fc_src1 = (const float*)d_in[10];
    const float* fc_dst1 = (const float*)d_in[11];
    const float* fc_e1 = (const float*)d_in[12];
    const float* attn_l1 = (const float*)d_in[13];
    const float* attn_r1 = (const float*)d_in[14];
    const float* attn_e1 = (const float*)d_in[15];
    const float* res_W1 = (const float*)d_in[16];
    const float* fc_src2 = (const float*)d_in[17];
    const float* fc_dst2 = (const float*)d_in[18];
    const float* attn_l2 = (const float*)d_in[19];
    const float* attn_r2 = (const float*)d_in[20];
    const float* res_W2 = (const float*)d_in[21];
    const float* W1 = (const float*)d_in[22];
    const float* b1 = (const float*)d_in[23];
    const float* W2 = (const float*)d_in[24];
    const float* b2 = (const float*)d_in[25];
    const int* src1 = (const int*)d_in[26];
    const int* dst1 = (const int*)d_in[27];
    const int* src2 = (const int*)d_in[28];
    const int* dst2 = (const int*)d_in[29];
    float* out = (float*)d_out;

    float* hlink = (float*)sym(g_hlink);
    float* hflow = (float*)sym(g_hflow);
    float* hp0 = (float*)sym(g_hp0);
    float* hp1 = (float*)sym(g_hp1);
    float* hp2 = (float*)sym(g_hp2);
    float* z1 = (float*)sym(g_z1);
    float* z2 = (float*)sym(g_z2);
    float* aggm = (float*)sym(g_aggm);
    float* x1 = (float*)sym(g_x1);
    uint32_t* hlinkp = (uint32_t*)sym(g_hlinkp);
    uint32_t* hflowp = (uint32_t*)sym(g_hflowp);
    uint32_t* hp0p = (uint32_t*)sym(g_hp0p);
    uint32_t* hp1p = (uint32_t*)sym(g_hp1p);
    uint32_t* hp2p = (uint32_t*)sym(g_hp2p);
    uint32_t* fc1p = (uint32_t*)sym(g_fc1p);
    uint32_t* fc2p = (uint32_t*)sym(g_fc2p);
    uint32_t* rw1p = (uint32_t*)sym(g_rw1p);
    uint32_t* rw2p = (uint32_t*)sym(g_rw2p);
    uint32_t* w1p = (uint32_t*)sym(g_w1p);
    float* vl1 = (float*)sym(g_vl1);
    float* vr1 = (float*)sym(g_vr1);
    float* vl2 = (float*)sym(g_vl2);
    float* vr2 = (float*)sym(g_vr2);
    float* ce = (float*)sym(g_ce);
    float* el = (float*)sym(g_el);
    float* er = (float*)sym(g_er);
    float* elog = (float*)sym(g_elog);
    float* denom = (float*)sym(g_denom);

    dim3 gz1(HDTOT / 128, (N_LINK + 127) / 128);
    dim3 gz2(HDTOT / 128, (N_FLOW + 127) / 128);
    dim3 gres(HID / 128, (N_PATH + 127) / 128);

    // weight packs (independent, issued first)
    pack_kernel<<<(HID * HDTOT + 255) / 256, 256>>>(fc_src2, fc2p, HID * HDTOT);
    pack_kernel<<<(HID * HDTOT + 255) / 256, 256>>>(fc_src1, fc1p, HID * HDTOT);
    pack_kernel<<<(HID * HID + 255) / 256, 256>>>(res_W1, rw1p, HID * HID);
    pack_kernel<<<(HID * HID + 255) / 256, 256>>>(res_W2, rw2p, HID * HID);
    pack_kernel<<<(3 * HID * HID + 255) / 256, 256>>>(W1, w1p, 3 * HID * HID);

    // per-type projections (emit fp32 + packed)
    proj_kernel<8><<<N_LINK, HID>>>(x_link, Wp_link, bp_link, hlink, hlinkp, N_LINK);
    proj_kernel<16><<<N_FLOW, HID>>>(x_flow, Wp_flow, bp_flow, hflow, hflowp, N_FLOW);
    proj_kernel<8><<<N_PATH, HID>>>(x_path, Wp_path, bp_path, hp0, hp0p, N_PATH);

    // big z2 GEMM early (independent of conv1)
    gemm_db16<<<gz2, 256>>>(hflowp, nullptr, nullptr, fc2p, z2, nullptr,
                            N_FLOW, HDTOT, 1, nullptr, nullptr, 0);
    attnvec_kernel<<<HID, 128>>>(fc_src2, attn_l2, vl2);
    attnvec_kernel<<<HID, 128>>>(fc_dst2, attn_r2, vr2);

    // ====================== conv1: link -> path ======================
    attnvec_kernel<<<HID, 128>>>(fc_src1, attn_l1, vl1);
    attnvec_kernel<<<HID, 128>>>(fc_dst1, attn_r1, vr1);
    attnvec_kernel<<<1, 128>>>(fc_e1, attn_e1, ce);

    gemm_db16<<<gz1, 256>>>(hlinkp, nullptr, nullptr, fc1p, z1, nullptr,
                            N_LINK, HDTOT, 1, nullptr, nullptr, 0);
    dotvec_kernel<<<N_LINK, 128>>>(hlink, vl1, el, N_LINK);
    dotvec_kernel<<<N_PATH, 128>>>(hp0, vr1, er, N_PATH);

    cudaMemsetAsync(denom, 0, (size_t)N_PATH * NH * sizeof(float));
    cudaMemsetAsync(aggm, 0, (size_t)N_PATH * HID * sizeof(float));

    edge_softmax_kernel<<<(E1 * NH + 255) / 256, 256>>>(src1, dst1, el, er, e2p, ce, elog, denom, E1, 1);
    aggregate_kernel<<<(E1 + 3) / 4, 256>>>(src1, dst1, elog, denom, z1, aggm, E1);

    // hp1 = relu(aggm + hp0 @ res_W1)
    gemm_db16<<<gres, 256>>>(hp0p, nullptr, nullptr, rw1p, hp1, hp1p,
                             N_PATH, HID, 1, aggm, nullptr, FLAG_RELU);

    // ====================== conv2: flow -> path ======================
    dotvec_kernel<<<N_FLOW, 128>>>(hflow, vl2, el, N_FLOW);
    dotvec_kernel<<<N_PATH, 128>>>(hp1, vr2, er, N_PATH);

    cudaMemsetAsync(denom, 0, (size_t)N_PATH * NH * sizeof(float));
    cudaMemsetAsync(aggm, 0, (size_t)N_PATH * HID * sizeof(float));

    edge_softmax_kernel<<<(E2 * NH + 255) / 256, 256>>>(src2, dst2, el, er, nullptr, ce, elog, denom, E2, 0);
    aggregate_kernel<<<(E2 + 3) / 4, 256>>>(src2, dst2, elog, denom, z2, aggm, E2);

    // hp2 = relu(aggm + hp1 @ res_W2)
    gemm_db16<<<gres, 256>>>(hp1p, nullptr, nullptr, rw2p, hp2, hp2p,
                             N_PATH, HID, 1, aggm, nullptr, FLAG_RELU);

    // ====================== decoder ======================
    // x1 = relu(concat(hp2, hp1, hp2) @ W1 + b1) as ONE segmented K=768 GEMM
    gemm_db16<<<gres, 256>>>(hp2p, hp1p, hp2p, w1p, x1, nullptr,
                             N_PATH, HID, 3, nullptr, b1, FLAG_RELU);

    // out = x1 @ W2 + b2
    final_kernel<<<(N_PATH * 32 + 255) / 256, 256>>>(x1, W2, b2, out, N_PATH);
}

// round 10
// speedup vs baseline: 1.5768x; 1.1207x over previous
#include <cuda_runtime.h>
#include <cuda_bf16.h>
#include <cstdint>

// Problem dims
#define N_LINK 2000
#define N_FLOW 30000
#define N_PATH 50000
#define E1 120000
#define E2 120000
#define HID 256
#define NH 4
#define HD 256
#define HDTOT 1024

// ---------------- scratch ------------------------------------------------------
__device__ float g_hp1[N_PATH * HID];          // fp32 (needed for er2 dot)
__device__ float g_z1[N_LINK * HDTOT];
__device__ float g_z2[N_FLOW * HDTOT];
__device__ float g_aggm1[N_PATH * HID];
__device__ float g_aggm2[N_PATH * HID];
__device__ float g_x1[N_PATH * HID];
__device__ uint32_t g_hlinkp[N_LINK * HID];
__device__ uint32_t g_hflowp[N_FLOW * HID];
__device__ uint32_t g_hp0p[N_PATH * HID];
__device__ uint32_t g_hp1p[N_PATH * HID];
__device__ uint32_t g_hp2p[N_PATH * HID];
__device__ uint32_t g_fc1p[HID * HDTOT];
__device__ uint32_t g_fc2p[HID * HDTOT];
__device__ uint32_t g_rw1p[HID * HID];
__device__ uint32_t g_rw2p[HID * HID];
__device__ uint32_t g_w1p[3 * HID * HID];
__device__ float g_vl1[HID * NH];
__device__ float g_vr1[HID * NH];
__device__ float g_vl2[HID * NH];
__device__ float g_vr2[HID * NH];
__device__ float g_ce[NH];
__device__ float g_el1[N_LINK * NH];
__device__ float g_er1[N_PATH * NH];
__device__ float g_el2[N_FLOW * NH];
__device__ float g_er2[N_PATH * NH];
__device__ float g_elog1[E1 * NH];
__device__ float g_elog2[E2 * NH];
__device__ float g_denom1[N_PATH * NH];
__device__ float g_denom2[N_PATH * NH];

// ---------------- packing ------------------------------------------------------
__device__ __forceinline__ uint32_t pack_split(float x) {
    __nv_bfloat16 h = __float2bfloat16_rn(x);
    float r = x - __bfloat162float(h);
    __nv_bfloat16 l = __float2bfloat16_rn(r);
    return ((uint32_t)__bfloat16_as_ushort(l) << 16) | (uint32_t)__bfloat16_as_ushort(h);
}

// one kernel packs all 5 weight matrices
#define PK0 (HID * HDTOT)            // fc_src1 -> fc1p
#define PK1 (PK0 + HID * HDTOT)      // fc_src2 -> fc2p
#define PK2 (PK1 + HID * HID)        // res_W1 -> rw1p
#define PK3 (PK2 + HID * HID)        // res_W2 -> rw2p
#define PKT (PK3 + 3 * HID * HID)    // W1 -> w1p
__global__ void pack_all_kernel(const float* __restrict__ fc1, const float* __restrict__ fc2,
                                const float* __restrict__ rw1, const float* __restrict__ rw2,
                                const float* __restrict__ w1,
                                uint32_t* __restrict__ fc1p, uint32_t* __restrict__ fc2p,
                                uint32_t* __restrict__ rw1p, uint32_t* __restrict__ rw2p,
                                uint32_t* __restrict__ w1p) {
    int i = blockIdx.x * blockDim.x + threadIdx.x;
    if (i >= PKT) return;
    if (i < PK0) fc1p[i] = pack_split(fc1[i]);
    else if (i < PK1) fc2p[i - PK0] = pack_split(fc2[i - PK0]);
    else if (i < PK2) rw1p[i - PK1] = pack_split(rw1[i - PK1]);
    else if (i < PK3) rw2p[i - PK2] = pack_split(rw2[i - PK2]);
    else w1p[i - PK3] = pack_split(w1[i - PK3]);
}

// batched attention-vector kernel: v[k*NH+h] = sum_d fc[k*1024+h*256+d]*attn[h*256+d]
// blockIdx.y selects which (fc, attn, out) triple; y==4 is fc_e1 (only k==0 valid)
__global__ void attnvec_all_kernel(
    const float* f0, const float* a0, float* v0,
    const float* f1, const float* a1, float* v1,
    const float* f2, const float* a2, float* v2,
    const float* f3, const float* a3, float* v3,
    const float* f4, const float* a4, float* v4) {
    int y = blockIdx.y;
    const float* fc; const float* attn; float* v;
    switch (y) {
        case 0: fc = f0; attn = a0; v = v0; break;
        case 1: fc = f1; attn = a1; v = v1; break;
        case 2: fc = f2; attn = a2; v = v2; break;
        case 3: fc = f3; attn = a3; v = v3; break;
        default: fc = f4; attn = a4; v = v4; break;
    }
    int k = blockIdx.x;
    if (y == 4 && k > 0) return;
    int h = threadIdx.x >> 5;
    int lane = threadIdx.x & 31;
    float s = 0.f;
    const float* fr = fc + (size_t)k * HDTOT + h * HD;
    const float* ar = attn + h * HD;
    for (int d = lane; d < HD; d += 32) s = fmaf(fr[d], ar[d], s);
#pragma unroll
    for (int o = 16; o; o >>= 1) s += __shfl_xor_sync(0xffffffffu, s, o);
    if (lane == 0) v[k * NH + h] = s;
}

// projection + relu + pack + fused (h @ vdot) per-row dot -> eout[n,h]
template <int K>
__global__ void proj_fused(const float* __restrict__ x, const float* __restrict__ W,
                           const float* __restrict__ b, uint32_t* __restrict__ outp,
                           const float* __restrict__ vdot, float* __restrict__ eout, int N) {
    __shared__ float xs[K];
    __shared__ float red[8][NH];
    int n = blockIdx.x;
    if (n >= N) return;
    int j = threadIdx.x;
    if (j < K) xs[j] = x[n * K + j];
    __syncthreads();
    float acc = b[j];
#pragma unroll
    for (int k = 0; k < K; k++) acc = fmaf(xs[k], W[k * HID + j], acc);
    acc = fmaxf(acc, 0.0f);
    outp[n * HID + j] = pack_split(acc);
    float p0 = acc * vdot[j * NH + 0];
    float p1 = acc * vdot[j * NH + 1];
    float p2 = acc * vdot[j * NH + 2];
    float p3 = acc * vdot[j * NH + 3];
#pragma unroll
    for (int o = 16; o; o >>= 1) {
        p0 += __shfl_xor_sync(0xffffffffu, p0, o);
        p1 += __shfl_xor_sync(0xffffffffu, p1, o);
        p2 += __shfl_xor_sync(0xffffffffu, p2, o);
        p3 += __shfl_xor_sync(0xffffffffu, p3, o);
    }
    int w = j >> 5, lane = j & 31;
    if (lane == 0) { red[w][0] = p0; red[w][1] = p1; red[w][2] = p2; red[w][3] = p3; }
    __syncthreads();
    if (j < NH) {
        float s = 0.f;
#pragma unroll
        for (int ww = 0; ww < 8; ww++) s += red[ww][j];
        eout[n * NH + j] = s;
    }
}

// er2 = hp1 @ vr2 (only remaining standalone dot kernel)
__global__ void dotvec_kernel(const float* __restrict__ hsrc, const float* __restrict__ v,
                              float* __restrict__ out, int N) {
    int n = blockIdx.x;
    if (n >= N) return;
    int h = threadIdx.x >> 5;
    int lane = threadIdx.x & 31;
    const float* hr = hsrc + (size_t)n * HID;
    float s = 0.f;
    for (int k = lane; k < HID; k += 32) s = fmaf(hr[k], v[k * NH + h], s);
#pragma unroll
    for (int o = 16; o; o >>= 1) s += __shfl_xor_sync(0xffffffffu, s, o);
    if (lane == 0) out[n * NH + h] = s;
}

// fused softmax numerator + denominator (max-shift dropped: logits O(0.1))
__global__ void edge_softmax_kernel(const int* __restrict__ src, const int* __restrict__ dst,
                                    const float* __restrict__ el, const float* __restrict__ er,
                                    const float* __restrict__ e2p, const float* __restrict__ ce,
                                    float* __restrict__ elog, float* __restrict__ denom,
                                    int E, int use_ee) {
    int i = blockIdx.x * blockDim.x + threadIdx.x;
    if (i >= E * NH) return;
    int e = i >> 2, h = i & 3;
    int s = src[e], t = dst[e];
    float v = el[s * NH + h] + er[t * NH + h];
    if (use_ee) v = fmaf(e2p[e], ce[h], v);
    v = (v > 0.f) ? v : 0.2f * v;
    float a = expf(v);
    elog[i] = a;
    atomicAdd(&denom[t * NH + h], a);
}

// aggregate (head mean fused), 4 edges per 256-thread block
__global__ void aggregate_kernel(const int* __restrict__ src, const int* __restrict__ dst,
                                 const float* __restrict__ anum, const float* __restrict__ denom,
                                 const float* __restrict__ z, float* __restrict__ aggm, int E) {
    __shared__ float al[4][NH];
    __shared__ int sidx[4], tidx[4];
    int e0 = blockIdx.x * 4;
    int tid = threadIdx.x;
    if (tid < 16) {
        int le = tid >> 2, h = tid & 3;
        int e = e0 + le;
        if (e < E) {
            int t = dst[e];
            float dn = denom[t * NH + h];
            al[le][h] = anum[e * NH + h] / fmaxf(dn, 1e-9f) * 0.25f;
            if (h == 0) { sidx[le] = src[e]; tidx[le] = t; }
        }
    }
    __syncthreads();
    int le = tid >> 6, t64 = tid & 63;
    int e = e0 + le;
    if (e >= E) return;
    int s = sidx[le], t = tidx[le];
    const float4* zr = (const float4*)(z + (size_t)s * HDTOT);
    float4 v = make_float4(0.f, 0.f, 0.f, 0.f);
#pragma unroll
    for (int h = 0; h < NH; h++) {
        float a = al[le][h];
        float4 zv = zr[h * 64 + t64];
        v.x = fmaf(a, zv.x, v.x);
        v.y = fmaf(a, zv.y, v.y);
        v.z = fmaf(a, zv.z, v.z);
        v.w = fmaf(a, zv.w, v.w);
    }
    float* p = aggm + (size_t)t * HID + t64 * 4;
    asm volatile("red.global.add.v4.f32 [%0], {%1,%2,%3,%4};"
                 :: "l"(p), "f"(v.x), "f"(v.y), "f"(v.z), "f"(v.w) : "memory");
}

// ---------------- dual-bf16 GEMM (R8, proven) ----------------------------------
#define FLAG_RELU 1
#define STAGES 2

__device__ __forceinline__ void mma_bf16(float* c, const uint32_t* a, const uint32_t* b) {
    asm volatile(
        "mma.sync.aligned.m16n8k16.row.col.f32.bf16.bf16.f32 "
        "{%0,%1,%2,%3}, {%4,%5,%6,%7}, {%8,%9}, {%0,%1,%2,%3};"
        : "+f"(c[0]), "+f"(c[1]), "+f"(c[2]), "+f"(c[3])
        : "r"(a[0]), "r"(a[1]), "r"(a[2]), "r"(a[3]), "r"(b[0]), "r"(b[1]));
}

__global__ __launch_bounds__(256) void gemm_db16(
    const uint32_t* __restrict__ A0, const uint32_t* __restrict__ A1p, const uint32_t* __restrict__ A2p,
    const uint32_t* __restrict__ B, float* __restrict__ C, uint32_t* __restrict__ Cp,
    int M, int N, int nseg,
    const float* __restrict__ addv, const float* __restrict__ bias, int flags) {
    __shared__ uint32_t As[STAGES][128][20];
    __shared__ uint32_t Bs[STAGES][16][136];

    int bm = blockIdx.y * 128, bn = blockIdx.x * 128;
    int tid = threadIdx.x;
    int w = tid >> 5, lane = tid & 31;
    int gid = lane >> 2, tig = lane & 3;
    int wm = (w >> 2) * 64, wn = (w & 3) * 32;

    int Ktot = nseg << 8;
    int ntile = Ktot >> 4;

    auto load_tile = [&](int slot, int t) {
        int k0 = t << 4;
        const uint32_t* A = (k0 < 256) ? A0 : (k0 < 512 ? A1p : A2p);
        int kk = k0 & 255;
#pragma unroll
        for (int it = 0; it < 2; it++) {
            int idx = tid + it * 256;
            int row = idx >> 2, qc = (idx & 3) * 4;
            int gr = bm + row;
            int grc = gr < M ? gr : 0;
            const uint32_t* g = A + (size_t)grc * 256 + kk + qc;
            uint32_t sa = (uint32_t)__cvta_generic_to_shared(&As[slot][row][qc]);
            asm volatile("cp.async.cg.shared.global [%0], [%1], 16, %2;"
                         :: "r"(sa), "l"(g), "r"(gr < M ? 16 : 0) : "memory");
            int brow = idx >> 5, nc = (idx & 31) * 4;
            const uint32_t* gB = B + (size_t)(k0 + brow) * N + bn + nc;
            uint32_t sb = (uint32_t)__cvta_generic_to_shared(&Bs[slot][brow][nc]);
            asm volatile("cp.async.cg.shared.global [%0], [%1], 16, 16;"
                         :: "r"(sb), "l"(gB) : "memory");
        }
    };

    float acc[4][4][4];
#pragma unroll
    for (int i = 0; i < 4; i++)
#pragma unroll
        for (int j = 0; j < 4; j++)
#pragma unroll
            for (int q = 0; q < 4; q++) acc[i][j][q] = 0.f;

    load_tile(0, 0);
    asm volatile("cp.async.commit_group;" ::: "memory");

    for (int t = 0; t < ntile; t++) {
        asm volatile("cp.async.wait_group 0;" ::: "memory");
        __syncthreads();
        int nt = t + 1;
        if (nt < ntile) {
            load_tile(nt & 1, nt);
            asm volatile("cp.async.commit_group;" ::: "memory");
        }
        int sl = t & 1;
#pragma unroll
        for (int ks = 0; ks < 16; ks += 8) {
            uint32_t b1r[4][2], b2r[4][2];
#pragma unroll
            for (int j = 0; j < 4; j++) {
                int c0 = wn + 8 * j + gid;
                uint32_t w0 = Bs[sl][ks + tig][c0];
                uint32_t w1 = Bs[sl][ks + tig + 4][c0];
                b1r[j][0] = __byte_perm(w0, w0, 0x1010);
                b1r[j][1] = __byte_perm(w1, w1, 0x1010);
                b2r[j][0] = w0 >> 16;
                b2r[j][1] = w1 >> 16;
            }
#pragma unroll
            for (int i = 0; i < 4; i++) {
                int r0 = wm + 16 * i + gid;
                uint32_t a1[4], a2[4];
                a1[0] = As[sl][r0][ks + tig];
                a1[1] = As[sl][r0 + 8][ks + tig];
                a1[2] = As[sl][r0][ks + tig + 4];
                a1[3] = As[sl][r0 + 8][ks + tig + 4];
#pragma unroll
                for (int q = 0; q < 4; q++) a2[q] = a1[q] & 0xFFFFu;
#pragma unroll
                for (int j = 0; j < 4; j++) {
                    mma_bf16(acc[i][j], a1, b1r[j]);
                    mma_bf16(acc[i][j], a2, b2r[j]);
                }
            }
        }
        __syncthreads();
    }

#pragma unroll
    for (int i = 0; i < 4; i++) {
#pragma unroll
        for (int j = 0; j < 4; j++) {
            int r0 = bm + wm + 16 * i + gid;
            int r1 = r0 + 8;
            int c = bn + wn + 8 * j + 2 * tig;
            float2 v0 = make_float2(acc[i][j][0], acc[i][j][1]);
            float2 v1 = make_float2(acc[i][j][2], acc[i][j][3]);
            float bx = 0.f, by = 0.f;
            if (bias) { bx = bias[c]; by = bias[c + 1]; }
            if (r0 < M) {
                size_t idx = (size_t)r0 * N + c;
                if (addv) { v0.x += addv[idx]; v0.y += addv[idx + 1]; }
                v0.x += bx; v0.y += by;
                if (flags & FLAG_RELU) { v0.x = fmaxf(v0.x, 0.f); v0.y = fmaxf(v0.y, 0.f); }
                if (C) *(float2*)(C + idx) = v0;
                if (Cp) { Cp[idx] = pack_split(v0.x); Cp[idx + 1] = pack_split(v0.y); }
            }
            if (r1 < M) {
                size_t idx = (size_t)r1 * N + c;
                if (addv) { v1.x += addv[idx]; v1.y += addv[idx + 1]; }
                v1.x += bx; v1.y += by;
                if (flags & FLAG_RELU) { v1.x = fmaxf(v1.x, 0.f); v1.y = fmaxf(v1.y, 0.f); }
                if (C) *(float2*)(C + idx) = v1;
                if (Cp) { Cp[idx] = pack_split(v1.x); Cp[idx + 1] = pack_split(v1.y); }
            }
        }
    }
}

// final: out[n,0:2] = x1[n,:]@W2[256,2] + b2
__global__ void final_kernel(const float* __restrict__ x1, const float* __restrict__ W2,
                             const float* __restrict__ b2, float* __restrict__ out, int N) {
    int warp = (blockIdx.x * blockDim.x + threadIdx.x) >> 5;
    int lane = threadIdx.x & 31;
    if (warp >= N) return;
    const float* xr = x1 + (size_t)warp * HID;
    float s0 = 0.f, s1 = 0.f;
    for (int k = lane; k < HID; k += 32) {
        float xv = xr[k];
        s0 = fmaf(xv, W2[k * 2 + 0], s0);
        s1 = fmaf(xv, W2[k * 2 + 1], s1);
    }
#pragma unroll
    for (int o = 16; o; o >>= 1) {
        s0 += __shfl_xor_sync(0xffffffffu, s0, o);
        s1 += __shfl_xor_sync(0xffffffffu, s1, o);
    }
    if (lane == 0) {
        out[warp * 2 + 0] = s0 + b2[0];
        out[warp * 2 + 1] = s1 + b2[1];
    }
}

// ---------------- host launcher -------------------------------------------------
static inline void* sym(const void* s) {
    void* p = nullptr;
    cudaGetSymbolAddress(&p, s);
    return p;
}

extern "C" void kernel_launch(void* const* d_in, const int* in_sizes, int n_in,
                              void* d_out, int out_size) {
    const float* x_link = (const float*)d_in[0];
    const float* x_flow = (const float*)d_in[1];
    const float* x_path = (const float*)d_in[2];
    const float* e2p = (const float*)d_in[3];
    const float* Wp_link = (const float*)d_in[4];
    const float* bp_link = (const float*)d_in[5];
    const float* Wp_flow = (const float*)d_in[6];
    const float* bp_flow = (const float*)d_in[7];
    const float* Wp_path = (const float*)d_in[8];
    const float* bp_path = (const float*)d_in[9];
    const float* fc_src1 = (const float*)d_in[10];
    const float* fc_dst1 = (const float*)d_in[11];
    const float* fc_e1 = (const float*)d_in[12];
    const float* attn_l1 = (const float*)d_in[13];
    const float* attn_r1 = (const float*)d_in[14];
    const float* attn_e1 = (const float*)d_in[15];
    const float* res_W1 = (const float*)d_in[16];
    const float* fc_src2 = (const float*)d_in[17];
    const float* fc_dst2 = (const float*)d_in[18];
    const float* attn_l2 = (const float*)d_in[19];
    const float* attn_r2 = (const float*)d_in[20];
    const float* res_W2 = (const float*)d_in[21];
    const float* W1 = (const float*)d_in[22];
    const float* b1 = (const float*)d_in[23];
    const float* W2 = (const float*)d_in[24];
    const float* b2 = (const float*)d_in[25];
    const int* src1 = (const int*)d_in[26];
    const int* dst1 = (const int*)d_in[27];
    const int* src2 = (const int*)d_in[28];
    const int* dst2 = (const int*)d_in[29];
    float* out = (float*)d_out;

    float* hp1 = (float*)sym(g_hp1);
    float* z1 = (float*)sym(g_z1);
    float* z2 = (float*)sym(g_z2);
    float* aggm1 = (float*)sym(g_aggm1);
    float* aggm2 = (float*)sym(g_aggm2);
    float* x1g = (float*)sym(g_x1);
    uint32_t* hlinkp = (uint32_t*)sym(g_hlinkp);
    uint32_t* hflowp = (uint32_t*)sym(g_hflowp);
    uint32_t* hp0p = (uint32_t*)sym(g_hp0p);
    uint32_t* hp1p = (uint32_t*)sym(g_hp1p);
    uint32_t* hp2p = (uint32_t*)sym(g_hp2p);
    uint32_t* fc1p = (uint32_t*)sym(g_fc1p);
    uint32_t* fc2p = (uint32_t*)sym(g_fc2p);
    uint32_t* rw1p = (uint32_t*)sym(g_rw1p);
    uint32_t* rw2p = (uint32_t*)sym(g_rw2p);
    uint32_t* w1p = (uint32_t*)sym(g_w1p);
    float* vl1 = (float*)sym(g_vl1);
    float* vr1 = (float*)sym(g_vr1);
    float* vl2 = (float*)sym(g_vl2);
    float* vr2 = (float*)sym(g_vr2);
    float* ce = (float*)sym(g_ce);
    float* el1 = (float*)sym(g_el1);
    float* er1 = (float*)sym(g_er1);
    float* el2 = (float*)sym(g_el2);
    float* er2 = (float*)sym(g_er2);
    float* elog1 = (float*)sym(g_elog1);
    float* elog2 = (float*)sym(g_elog2);
    float* denom1 = (float*)sym(g_denom1);
    float* denom2 = (float*)sym(g_denom2);

    // fork/join resources (created per call; kernel_launch runs only a few times)
    cudaStream_t sB;
    cudaStreamCreateWithFlags(&sB, cudaStreamNonBlocking);
    cudaEvent_t evFork, evJoin;
    cudaEventCreateWithFlags(&evFork, cudaEventDisableTiming);
    cudaEventCreateWithFlags(&evJoin, cudaEventDisableTiming);

    dim3 gz1(HDTOT / 128, (N_LINK + 127) / 128);
    dim3 gz2(HDTOT / 128, (N_FLOW + 127) / 128);
    dim3 gres(HID / 128, (N_PATH + 127) / 128);

    // ---------- shared prologue (main stream) ----------
    attnvec_all_kernel<<<dim3(HID, 5), 128>>>(
        fc_src1, attn_l1, vl1, fc_dst1, attn_r1, vr1,
        fc_src2, attn_l2, vl2, fc_dst2, attn_r2, vr2,
        fc_e1, attn_e1, ce);
    pack_all_kernel<<<(PKT + 255) / 256, 256>>>(fc_src1, fc_src2, res_W1, res_W2, W1,
                                                fc1p, fc2p, rw1p, rw2p, w1p);
    cudaMemsetAsync(denom1, 0, (size_t)N_PATH * NH * sizeof(float));
    cudaMemsetAsync(aggm1, 0, (size_t)N_PATH * HID * sizeof(float));
    cudaMemsetAsync(denom2, 0, (size_t)N_PATH * NH * sizeof(float));
    cudaMemsetAsync(aggm2, 0, (size_t)N_PATH * HID * sizeof(float));

    // ---------- fork: stream B runs the full conv1 chain ----------
    cudaEventRecord(evFork, 0);
    cudaStreamWaitEvent(sB, evFork, 0);

    proj_fused<8><<<N_LINK, HID, 0, sB>>>(x_link, Wp_link, bp_link, hlinkp, vl1, el1, N_LINK);
    proj_fused<8><<<N_PATH, HID, 0, sB>>>(x_path, Wp_path, bp_path, hp0p, vr1, er1, N_PATH);
    gemm_db16<<<gz1, 256, 0, sB>>>(hlinkp, nullptr, nullptr, fc1p, z1, nullptr,
                                   N_LINK, HDTOT, 1, nullptr, nullptr, 0);
    edge_softmax_kernel<<<(E1 * NH + 255) / 256, 256, 0, sB>>>(
        src1, dst1, el1, er1, e2p, ce, elog1, denom1, E1, 1);
    aggregate_kernel<<<(E1 + 3) / 4, 256, 0, sB>>>(src1, dst1, elog1, denom1, z1, aggm1, E1);
    // hp1 = relu(aggm1 + hp0 @ res_W1)  (fp32 + packed)
    gemm_db16<<<gres, 256, 0, sB>>>(hp0p, nullptr, nullptr, rw1p, hp1, hp1p,
                                    N_PATH, HID, 1, aggm1, nullptr, FLAG_RELU);
    dotvec_kernel<<<N_PATH, 128, 0, sB>>>(hp1, vr2, er2, N_PATH);
    cudaEventRecord(evJoin, sB);

    // ---------- main stream: flow proj + big z2 GEMM (overlaps with conv1) ----------
    proj_fused<16><<<N_FLOW, HID>>>(x_flow, Wp_flow, bp_flow, hflowp, vl2, el2, N_FLOW);
    gemm_db16<<<gz2, 256>>>(hflowp, nullptr, nullptr, fc2p, z2, nullptr,
                            N_FLOW, HDTOT, 1, nullptr, nullptr, 0);

    // ---------- join, then conv2 + decoder ----------
    cudaStreamWaitEvent(0, evJoin, 0);

    edge_softmax_kernel<<<(E2 * NH + 255) / 256, 256>>>(
        src2, dst2, el2, er2, nullptr, ce, elog2, denom2, E2, 0);
    aggregate_kernel<<<(E2 + 3) / 4, 256>>>(src2, dst2, elog2, denom2, z2, aggm2, E2);

    // hp2 = relu(aggm2 + hp1 @ res_W2)  (packed only; fp32 not needed downstream)
    gemm_db16<<<gres, 256>>>(hp1p, nullptr, nullptr, rw2p, nullptr, hp2p,
                             N_PATH, HID, 1, aggm2, nullptr, FLAG_RELU);

    // x1 = relu(concat(hp2, hp1, hp2) @ W1 + b1) as ONE segmented K=768 GEMM
    gemm_db16<<<gres, 256>>>(hp2p, hp1p, hp2p, w1p, x1g, nullptr,
                             N_PATH, HID, 3, nullptr, b1, FLAG_RELU);

    // out = x1 @ W2 + b2
    final_kernel<<<(N_PATH * 32 + 255) / 256, 256>>>(x1g, W2, b2, out, N_PATH);
}

// round 11
// speedup vs baseline: 1.7946x; 1.1381x over previous
#include <cuda_runtime.h>
#include <cuda_bf16.h>
#include <cstdint>

// Problem dims
#define N_LINK 2000
#define N_FLOW 30000
#define N_PATH 50000
#define E1 120000
#define E2 120000
#define HID 256
#define NH 4
#define HD 256
#define HDTOT 1024

// ---------------- scratch ------------------------------------------------------
__device__ float g_hp1[N_PATH * HID];          // fp32 (needed for er2 dot)
__device__ float g_z1[N_LINK * HDTOT];
__device__ float g_z2[N_FLOW * HDTOT];
__device__ float g_aggm1[N_PATH * HID];
__device__ float g_aggm2[N_PATH * HID];
__device__ float g_x1[N_PATH * HID];
__device__ uint32_t g_hlinkp[N_LINK * HID];
__device__ uint32_t g_hflowp[N_FLOW * HID];
__device__ uint32_t g_hp0p[N_PATH * HID];
__device__ uint32_t g_hp1p[N_PATH * HID];
__device__ uint32_t g_hp2p[N_PATH * HID];
__device__ uint32_t g_fc1p[HID * HDTOT];
__device__ uint32_t g_fc2p[HID * HDTOT];
__device__ uint32_t g_rw1p[HID * HID];
__device__ uint32_t g_rw2p[HID * HID];
__device__ uint32_t g_w1p[3 * HID * HID];
__device__ float g_vl1[HID * NH];
__device__ float g_vr1[HID * NH];
__device__ float g_vl2[HID * NH];
__device__ float g_vr2[HID * NH];
__device__ float g_ce[NH];
__device__ float g_el1[N_LINK * NH];
__device__ float g_er1[N_PATH * NH];
__device__ float g_el2[N_FLOW * NH];
__device__ float g_er2[N_PATH * NH];
__device__ float g_elog1[E1 * NH];
__device__ float g_elog2[E2 * NH];
__device__ float g_denom1[N_PATH * NH];
__device__ float g_denom2[N_PATH * NH];

// ---------------- packing ------------------------------------------------------
__device__ __forceinline__ uint32_t pack_split(float x) {
    __nv_bfloat16 h = __float2bfloat16_rn(x);
    float r = x - __bfloat162float(h);
    __nv_bfloat16 l = __float2bfloat16_rn(r);
    return ((uint32_t)__bfloat16_as_ushort(l) << 16) | (uint32_t)__bfloat16_as_ushort(h);
}

// one kernel packs all 5 weight matrices
#define PK0 (HID * HDTOT)
#define PK1 (PK0 + HID * HDTOT)
#define PK2 (PK1 + HID * HID)
#define PK3 (PK2 + HID * HID)
#define PKT (PK3 + 3 * HID * HID)
__global__ void pack_all_kernel(const float* __restrict__ fc1, const float* __restrict__ fc2,
                                const float* __restrict__ rw1, const float* __restrict__ rw2,
                                const float* __restrict__ w1,
                                uint32_t* __restrict__ fc1p, uint32_t* __restrict__ fc2p,
                                uint32_t* __restrict__ rw1p, uint32_t* __restrict__ rw2p,
                                uint32_t* __restrict__ w1p) {
    int i = blockIdx.x * blockDim.x + threadIdx.x;
    if (i >= PKT) return;
    if (i < PK0) fc1p[i] = pack_split(fc1[i]);
    else if (i < PK1) fc2p[i - PK0] = pack_split(fc2[i - PK0]);
    else if (i < PK2) rw1p[i - PK1] = pack_split(rw1[i - PK1]);
    else if (i < PK3) rw2p[i - PK2] = pack_split(rw2[i - PK2]);
    else w1p[i - PK3] = pack_split(w1[i - PK3]);
}

// batched attention-vector kernel
__global__ void attnvec_all_kernel(
    const float* f0, const float* a0, float* v0,
    const float* f1, const float* a1, float* v1,
    const float* f2, const float* a2, float* v2,
    const float* f3, const float* a3, float* v3,
    const float* f4, const float* a4, float* v4) {
    int y = blockIdx.y;
    const float* fc; const float* attn; float* v;
    switch (y) {
        case 0: fc = f0; attn = a0; v = v0; break;
        case 1: fc = f1; attn = a1; v = v1; break;
        case 2: fc = f2; attn = a2; v = v2; break;
        case 3: fc = f3; attn = a3; v = v3; break;
        default: fc = f4; attn = a4; v = v4; break;
    }
    int k = blockIdx.x;
    if (y == 4 && k > 0) return;
    int h = threadIdx.x >> 5;
    int lane = threadIdx.x & 31;
    float s = 0.f;
    const float* fr = fc + (size_t)k * HDTOT + h * HD;
    const float* ar = attn + h * HD;
    for (int d = lane; d < HD; d += 32) s = fmaf(fr[d], ar[d], s);
#pragma unroll
    for (int o = 16; o; o >>= 1) s += __shfl_xor_sync(0xffffffffu, s, o);
    if (lane == 0) v[k * NH + h] = s;
}

// row-tiled projection: 32 rows/block, W column + vdot in registers,
// x rows staged in shared, coalesced packed stores, fused per-row dot.
#define PROJ_R 32
template <int K>
__global__ __launch_bounds__(256) void proj_tiled(
    const float* __restrict__ x, const float* __restrict__ W,
    const float* __restrict__ b, uint32_t* __restrict__ outp,
    const float* __restrict__ vdot, float* __restrict__ eout, int N) {
    __shared__ float xs[PROJ_R][K];
    __shared__ float redm[2][8][NH];
    int n0 = blockIdx.x * PROJ_R;
    int j = threadIdx.x;
    float wreg[K];
#pragma unroll
    for (int k = 0; k < K; k++) wreg[k] = W[k * HID + j];
    float breg = b[j];
    float v0 = vdot[j * NH + 0], v1 = vdot[j * NH + 1];
    float v2 = vdot[j * NH + 2], v3 = vdot[j * NH + 3];
    for (int i = j; i < PROJ_R * K; i += 256) {
        int r = i / K, k = i % K;
        int n = n0 + r;
        xs[r][k] = (n < N) ? x[(size_t)n * K + k] : 0.f;
    }
    __syncthreads();
    int w = j >> 5, lane = j & 31;
    for (int r = 0; r < PROJ_R; r++) {
        int n = n0 + r;
        if (n >= N) break;  // uniform across block
        float acc = breg;
#pragma unroll
        for (int k = 0; k < K; k++) acc = fmaf(xs[r][k], wreg[k], acc);
        acc = fmaxf(acc, 0.0f);
        outp[(size_t)n * HID + j] = pack_split(acc);
        float p0 = acc * v0, p1 = acc * v1, p2 = acc * v2, p3 = acc * v3;
#pragma unroll
        for (int o = 16; o; o >>= 1) {
            p0 += __shfl_xor_sync(0xffffffffu, p0, o);
            p1 += __shfl_xor_sync(0xffffffffu, p1, o);
            p2 += __shfl_xor_sync(0xffffffffu, p2, o);
            p3 += __shfl_xor_sync(0xffffffffu, p3, o);
        }
        int par = r & 1;
        if (lane == 0) {
            redm[par][w][0] = p0; redm[par][w][1] = p1;
            redm[par][w][2] = p2; redm[par][w][3] = p3;
        }
        __syncthreads();
        if (j < NH) {
            float s = 0.f;
#pragma unroll
            for (int ww = 0; ww < 8; ww++) s += redm[par][ww][j];
            eout[(size_t)n * NH + j] = s;
        }
    }
}

// er2 = hp1 @ vr2
__global__ void dotvec_kernel(const float* __restrict__ hsrc, const float* __restrict__ v,
                              float* __restrict__ out, int N) {
    int n = blockIdx.x;
    if (n >= N) return;
    int h = threadIdx.x >> 5;
    int lane = threadIdx.x & 31;
    const float* hr = hsrc + (size_t)n * HID;
    float s = 0.f;
    for (int k = lane; k < HID; k += 32) s = fmaf(hr[k], v[k * NH + h], s);
#pragma unroll
    for (int o = 16; o; o >>= 1) s += __shfl_xor_sync(0xffffffffu, s, o);
    if (lane == 0) out[n * NH + h] = s;
}

// fused softmax numerator + denominator (max-shift dropped: logits O(0.1))
__global__ void edge_softmax_kernel(const int* __restrict__ src, const int* __restrict__ dst,
                                    const float* __restrict__ el, const float* __restrict__ er,
                                    const float* __restrict__ e2p, const float* __restrict__ ce,
                                    float* __restrict__ elog, float* __restrict__ denom,
                                    int E, int use_ee) {
    int i = blockIdx.x * blockDim.x + threadIdx.x;
    if (i >= E * NH) return;
    int e = i >> 2, h = i & 3;
    int s = src[e], t = dst[e];
    float v = el[s * NH + h] + er[t * NH + h];
    if (use_ee) v = fmaf(e2p[e], ce[h], v);
    v = (v > 0.f) ? v : 0.2f * v;
    float a = expf(v);
    elog[i] = a;
    atomicAdd(&denom[t * NH + h], a);
}

// aggregate (head mean fused), 4 edges per 256-thread block
__global__ void aggregate_kernel(const int* __restrict__ src, const int* __restrict__ dst,
                                 const float* __restrict__ anum, const float* __restrict__ denom,
                                 const float* __restrict__ z, float* __restrict__ aggm, int E) {
    __shared__ float al[4][NH];
    __shared__ int sidx[4], tidx[4];
    int e0 = blockIdx.x * 4;
    int tid = threadIdx.x;
    if (tid < 16) {
        int le = tid >> 2, h = tid & 3;
        int e = e0 + le;
        if (e < E) {
            int t = dst[e];
            float dn = denom[t * NH + h];
            al[le][h] = anum[e * NH + h] / fmaxf(dn, 1e-9f) * 0.25f;
            if (h == 0) { sidx[le] = src[e]; tidx[le] = t; }
        }
    }
    __syncthreads();
    int le = tid >> 6, t64 = tid & 63;
    int e = e0 + le;
    if (e >= E) return;
    int s = sidx[le], t = tidx[le];
    const float4* zr = (const float4*)(z + (size_t)s * HDTOT);
    float4 v = make_float4(0.f, 0.f, 0.f, 0.f);
#pragma unroll
    for (int h = 0; h < NH; h++) {
        float a = al[le][h];
        float4 zv = zr[h * 64 + t64];
        v.x = fmaf(a, zv.x, v.x);
        v.y = fmaf(a, zv.y, v.y);
        v.z = fmaf(a, zv.z, v.z);
        v.w = fmaf(a, zv.w, v.w);
    }
    float* p = aggm + (size_t)t * HID + t64 * 4;
    asm volatile("red.global.add.v4.f32 [%0], {%1,%2,%3,%4};"
                 :: "l"(p), "f"(v.x), "f"(v.y), "f"(v.z), "f"(v.w) : "memory");
}

// ---------------- dual-bf16 GEMM with paired-lo (3 mmas / 16 real k) -----------
// Per 16 real k per output fragment:
//   mma1a: A=(hi,lo)[k 0..7]   x B=(hi,hi)[k 0..7]   -> hi*hi + lo_a*hi_b
//   mma1b: same for k 8..15
//   mma2 : A=(hi[k],hi[k+8])   x B=(lo[k],lo[k+8])   -> hi_a*lo_b for all 16 k
#define FLAG_RELU 1
#define STAGES 2

__device__ __forceinline__ void mma_bf16(float* c, const uint32_t* a, const uint32_t* b) {
    asm volatile(
        "mma.sync.aligned.m16n8k16.row.col.f32.bf16.bf16.f32 "
        "{%0,%1,%2,%3}, {%4,%5,%6,%7}, {%8,%9}, {%0,%1,%2,%3};"
        : "+f"(c[0]), "+f"(c[1]), "+f"(c[2]), "+f"(c[3])
        : "r"(a[0]), "r"(a[1]), "r"(a[2]), "r"(a[3]), "r"(b[0]), "r"(b[1]));
}

__global__ __launch_bounds__(256) void gemm_db16(
    const uint32_t* __restrict__ A0, const uint32_t* __restrict__ A1p, const uint32_t* __restrict__ A2p,
    const uint32_t* __restrict__ B, float* __restrict__ C, uint32_t* __restrict__ Cp,
    int M, int N, int nseg,
    const float* __restrict__ addv, const float* __restrict__ bias, int flags) {
    __shared__ uint32_t As[STAGES][128][20];
    __shared__ uint32_t Bs[STAGES][16][136];

    int bm = blockIdx.y * 128, bn = blockIdx.x * 128;
    int tid = threadIdx.x;
    int w = tid >> 5, lane = tid & 31;
    int gid = lane >> 2, tig = lane & 3;
    int wm = (w >> 2) * 64, wn = (w & 3) * 32;

    int Ktot = nseg << 8;
    int ntile = Ktot >> 4;

    auto load_tile = [&](int slot, int t) {
        int k0 = t << 4;
        const uint32_t* A = (k0 < 256) ? A0 : (k0 < 512 ? A1p : A2p);
        int kk = k0 & 255;
#pragma unroll
        for (int it = 0; it < 2; it++) {
            int idx = tid + it * 256;
            int row = idx >> 2, qc = (idx & 3) * 4;
            int gr = bm + row;
            int grc = gr < M ? gr : 0;
            const uint32_t* g = A + (size_t)grc * 256 + kk + qc;
            uint32_t sa = (uint32_t)__cvta_generic_to_shared(&As[slot][row][qc]);
            asm volatile("cp.async.cg.shared.global [%0], [%1], 16, %2;"
                         :: "r"(sa), "l"(g), "r"(gr < M ? 16 : 0) : "memory");
            int brow = idx >> 5, nc = (idx & 31) * 4;
            const uint32_t* gB = B + (size_t)(k0 + brow) * N + bn + nc;
            uint32_t sb = (uint32_t)__cvta_generic_to_shared(&Bs[slot][brow][nc]);
            asm volatile("cp.async.cg.shared.global [%0], [%1], 16, 16;"
                         :: "r"(sb), "l"(gB) : "memory");
        }
    };

    float acc[4][4][4];
#pragma unroll
    for (int i = 0; i < 4; i++)
#pragma unroll
        for (int j = 0; j < 4; j++)
#pragma unroll
            for (int q = 0; q < 4; q++) acc[i][j][q] = 0.f;

    load_tile(0, 0);
    asm volatile("cp.async.commit_group;" ::: "memory");

    for (int t = 0; t < ntile; t++) {
        asm volatile("cp.async.wait_group 0;" ::: "memory");
        __syncthreads();
        int nt = t + 1;
        if (nt < ntile) {
            load_tile(nt & 1, nt);
            asm volatile("cp.async.commit_group;" ::: "memory");
        }
        int sl = t & 1;
        // B fragments for the whole 16-real-k tile
        uint32_t b1a[4][2], b1b[4][2], b2f[4][2];
#pragma unroll
        for (int j = 0; j < 4; j++) {
            int c0 = wn + 8 * j + gid;
            uint32_t w00 = Bs[sl][tig][c0];
            uint32_t w01 = Bs[sl][tig + 4][c0];
            uint32_t w10 = Bs[sl][tig + 8][c0];
            uint32_t w11 = Bs[sl][tig + 12][c0];
            b1a[j][0] = __byte_perm(w00, w00, 0x1010);
            b1a[j][1] = __byte_perm(w01, w01, 0x1010);
            b1b[j][0] = __byte_perm(w10, w10, 0x1010);
            b1b[j][1] = __byte_perm(w11, w11, 0x1010);
            b2f[j][0] = __byte_perm(w00, w10, 0x7632);
            b2f[j][1] = __byte_perm(w01, w11, 0x7632);
        }
#pragma unroll
        for (int i = 0; i < 4; i++) {
            int r0 = wm + 16 * i + gid;
            uint32_t u00 = As[sl][r0][tig];
            uint32_t u01 = As[sl][r0][tig + 4];
            uint32_t u02 = As[sl][r0][tig + 8];
            uint32_t u03 = As[sl][r0][tig + 12];
            uint32_t u10 = As[sl][r0 + 8][tig];
            uint32_t u11 = As[sl][r0 + 8][tig + 4];
            uint32_t u12 = As[sl][r0 + 8][tig + 8];
            uint32_t u13 = As[sl][r0 + 8][tig + 12];
            uint32_t a1a[4] = {u00, u10, u01, u11};
            uint32_t a1b[4] = {u02, u12, u03, u13};
            uint32_t a2[4] = {__byte_perm(u00, u02, 0x5410), __byte_perm(u10, u12, 0x5410),
                              __byte_perm(u01, u03, 0x5410), __byte_perm(u11, u13, 0x5410)};
#pragma unroll
            for (int j = 0; j < 4; j++) {
                mma_bf16(acc[i][j], a1a, b1a[j]);
                mma_bf16(acc[i][j], a1b, b1b[j]);
                mma_bf16(acc[i][j], a2, b2f[j]);
            }
        }
        __syncthreads();
    }

#pragma unroll
    for (int i = 0; i < 4; i++) {
#pragma unroll
        for (int j = 0; j < 4; j++) {
            int r0 = bm + wm + 16 * i + gid;
            int r1 = r0 + 8;
            int c = bn + wn + 8 * j + 2 * tig;
            float2 v0 = make_float2(acc[i][j][0], acc[i][j][1]);
            float2 v1 = make_float2(acc[i][j][2], acc[i][j][3]);
            float bx = 0.f, by = 0.f;
            if (bias) { bx = bias[c]; by = bias[c + 1]; }
            if (r0 < M) {
                size_t idx = (size_t)r0 * N + c;
                if (addv) { v0.x += addv[idx]; v0.y += addv[idx + 1]; }
                v0.x += bx; v0.y += by;
                if (flags & FLAG_RELU) { v0.x = fmaxf(v0.x, 0.f); v0.y = fmaxf(v0.y, 0.f); }
                if (C) *(float2*)(C + idx) = v0;
                if (Cp) { Cp[idx] = pack_split(v0.x); Cp[idx + 1] = pack_split(v0.y); }
            }
            if (r1 < M) {
                size_t idx = (size_t)r1 * N + c;
                if (addv) { v1.x += addv[idx]; v1.y += addv[idx + 1]; }
                v1.x += bx; v1.y += by;
                if (flags & FLAG_RELU) { v1.x = fmaxf(v1.x, 0.f); v1.y = fmaxf(v1.y, 0.f); }
                if (C) *(float2*)(C + idx) = v1;
                if (Cp) { Cp[idx] = pack_split(v1.x); Cp[idx + 1] = pack_split(v1.y); }
            }
        }
    }
}

// final: out[n,0:2] = x1[n,:]@W2[256,2] + b2
__global__ void final_kernel(const float* __restrict__ x1, const float* __restrict__ W2,
                             const float* __restrict__ b2, float* __restrict__ out, int N) {
    int warp = (blockIdx.x * blockDim.x + threadIdx.x) >> 5;
    int lane = threadIdx.x & 31;
    if (warp >= N) return;
    const float* xr = x1 + (size_t)warp * HID;
    float s0 = 0.f, s1 = 0.f;
    for (int k = lane; k < HID; k += 32) {
        float xv = xr[k];
        s0 = fmaf(xv, W2[k * 2 + 0], s0);
        s1 = fmaf(xv, W2[k * 2 + 1], s1);
    }
#pragma unroll
    for (int o = 16; o; o >>= 1) {
        s0 += __shfl_xor_sync(0xffffffffu, s0, o);
        s1 += __shfl_xor_sync(0xffffffffu, s1, o);
    }
    if (lane == 0) {
        out[warp * 2 + 0] = s0 + b2[0];
        out[warp * 2 + 1] = s1 + b2[1];
    }
}

// ---------------- host launcher -------------------------------------------------
static inline void* sym(const void* s) {
    void* p = nullptr;
    cudaGetSymbolAddress(&p, s);
    return p;
}

extern "C" void kernel_launch(void* const* d_in, const int* in_sizes, int n_in,
                              void* d_out, int out_size) {
    const float* x_link = (const float*)d_in[0];
    const float* x_flow = (const float*)d_in[1];
    const float* x_path = (const float*)d_in[2];
    const float* e2p = (const float*)d_in[3];
    const float* Wp_link = (const float*)d_in[4];
    const float* bp_link = (const float*)d_in[5];
    const float* Wp_flow = (const float*)d_in[6];
    const float* bp_flow = (const float*)d_in[7];
    const float* Wp_path = (const float*)d_in[8];
    const float* bp_path = (const float*)d_in[9];
    const float* fc_src1 = (const float*)d_in[10];
    const float* fc_dst1 = (const float*)d_in[11];
    const float* fc_e1 = (const float*)d_in[12];
    const float* attn_l1 = (const float*)d_in[13];
    const float* attn_r1 = (const float*)d_in[14];
    const float* attn_e1 = (const float*)d_in[15];
    const float* res_W1 = (const float*)d_in[16];
    const float* fc_src2 = (const float*)d_in[17];
    const float* fc_dst2 = (const float*)d_in[18];
    const float* attn_l2 = (const float*)d_in[19];
    const float* attn_r2 = (const float*)d_in[20];
    const float* res_W2 = (const float*)d_in[21];
    const float* W1 = (const float*)d_in[22];
    const float* b1 = (const float*)d_in[23];
    const float* W2 = (const float*)d_in[24];
    const float* b2 = (const float*)d_in[25];
    const int* src1 = (const int*)d_in[26];
    const int* dst1 = (const int*)d_in[27];
    const int* src2 = (const int*)d_in[28];
    const int* dst2 = (const int*)d_in[29];
    float* out = (float*)d_out;

    float* hp1 = (float*)sym(g_hp1);
    float* z1 = (float*)sym(g_z1);
    float* z2 = (float*)sym(g_z2);
    float* aggm1 = (float*)sym(g_aggm1);
    float* aggm2 = (float*)sym(g_aggm2);
    float* x1g = (float*)sym(g_x1);
    uint32_t* hlinkp = (uint32_t*)sym(g_hlinkp);
    uint32_t* hflowp = (uint32_t*)sym(g_hflowp);
    uint32_t* hp0p = (uint32_t*)sym(g_hp0p);
    uint32_t* hp1p = (uint32_t*)sym(g_hp1p);
    uint32_t* hp2p = (uint32_t*)sym(g_hp2p);
    uint32_t* fc1p = (uint32_t*)sym(g_fc1p);
    uint32_t* fc2p = (uint32_t*)sym(g_fc2p);
    uint32_t* rw1p = (uint32_t*)sym(g_rw1p);
    uint32_t* rw2p = (uint32_t*)sym(g_rw2p);
    uint32_t* w1p = (uint32_t*)sym(g_w1p);
    float* vl1 = (float*)sym(g_vl1);
    float* vr1 = (float*)sym(g_vr1);
    float* vl2 = (float*)sym(g_vl2);
    float* vr2 = (float*)sym(g_vr2);
    float* ce = (float*)sym(g_ce);
    float* el1 = (float*)sym(g_el1);
    float* er1 = (float*)sym(g_er1);
    float* el2 = (float*)sym(g_el2);
    float* er2 = (float*)sym(g_er2);
    float* elog1 = (float*)sym(g_elog1);
    float* elog2 = (float*)sym(g_elog2);
    float* denom1 = (float*)sym(g_denom1);
    float* denom2 = (float*)sym(g_denom2);

    cudaStream_t sB;
    cudaStreamCreateWithFlags(&sB, cudaStreamNonBlocking);
    cudaEvent_t evFork, evJoin;
    cudaEventCreateWithFlags(&evFork, cudaEventDisableTiming);
    cudaEventCreateWithFlags(&evJoin, cudaEventDisableTiming);

    dim3 gz1(HDTOT / 128, (N_LINK + 127) / 128);
    dim3 gz2(HDTOT / 128, (N_FLOW + 127) / 128);
    dim3 gres(HID / 128, (N_PATH + 127) / 128);

    // ---------- shared prologue (main stream) ----------
    attnvec_all_kernel<<<dim3(HID, 5), 128>>>(
        fc_src1, attn_l1, vl1, fc_dst1, attn_r1, vr1,
        fc_src2, attn_l2, vl2, fc_dst2, attn_r2, vr2,
        fc_e1, attn_e1, ce);
    pack_all_kernel<<<(PKT + 255) / 256, 256>>>(fc_src1, fc_src2, res_W1, res_W2, W1,
                                                fc1p, fc2p, rw1p, rw2p, w1p);
    cudaMemsetAsync(denom1, 0, (size_t)N_PATH * NH * sizeof(float));
    cudaMemsetAsync(aggm1, 0, (size_t)N_PATH * HID * sizeof(float));
    cudaMemsetAsync(denom2, 0, (size_t)N_PATH * NH * sizeof(float));
    cudaMemsetAsync(aggm2, 0, (size_t)N_PATH * HID * sizeof(float));

    // ---------- fork: stream B runs the full conv1 chain ----------
    cudaEventRecord(evFork, 0);
    cudaStreamWaitEvent(sB, evFork, 0);

    proj_tiled<8><<<(N_LINK + PROJ_R - 1) / PROJ_R, 256, 0, sB>>>(
        x_link, Wp_link, bp_link, hlinkp, vl1, el1, N_LINK);
    proj_tiled<8><<<(N_PATH + PROJ_R - 1) / PROJ_R, 256, 0, sB>>>(
        x_path, Wp_path, bp_path, hp0p, vr1, er1, N_PATH);
    gemm_db16<<<gz1, 256, 0, sB>>>(hlinkp, nullptr, nullptr, fc1p, z1, nullptr,
                                   N_LINK, HDTOT, 1, nullptr, nullptr, 0);
    edge_softmax_kernel<<<(E1 * NH + 255) / 256, 256, 0, sB>>>(
        src1, dst1, el1, er1, e2p, ce, elog1, denom1, E1, 1);
    aggregate_kernel<<<(E1 + 3) / 4, 256, 0, sB>>>(src1, dst1, elog1, denom1, z1, aggm1, E1);
    gemm_db16<<<gres, 256, 0, sB>>>(hp0p, nullptr, nullptr, rw1p, hp1, hp1p,
                                    N_PATH, HID, 1, aggm1, nullptr, FLAG_RELU);
    dotvec_kernel<<<N_PATH, 128, 0, sB>>>(hp1, vr2, er2, N_PATH);
    cudaEventRecord(evJoin, sB);

    // ---------- main stream: flow proj + big z2 GEMM ----------
    proj_tiled<16><<<(N_FLOW + PROJ_R - 1) / PROJ_R, 256>>>(
        x_flow, Wp_flow, bp_flow, hflowp, vl2, el2, N_FLOW);
    gemm_db16<<<gz2, 256>>>(hflowp, nullptr, nullptr, fc2p, z2, nullptr,
                            N_FLOW, HDTOT, 1, nullptr, nullptr, 0);

    // ---------- join, then conv2 + decoder ----------
    cudaStreamWaitEvent(0, evJoin, 0);

    edge_softmax_kernel<<<(E2 * NH + 255) / 256, 256>>>(
        src2, dst2, el2, er2, nullptr, ce, elog2, denom2, E2, 0);
    aggregate_kernel<<<(E2 + 3) / 4, 256>>>(src2, dst2, elog2, denom2, z2, aggm2, E2);

    gemm_db16<<<gres, 256>>>(hp1p, nullptr, nullptr, rw2p, nullptr, hp2p,
                             N_PATH, HID, 1, aggm2, nullptr, FLAG_RELU);

    gemm_db16<<<gres, 256>>>(hp2p, hp1p, hp2p, w1p, x1g, nullptr,
                             N_PATH, HID, 3, nullptr, b1, FLAG_RELU);

    final_kernel<<<(N_PATH * 32 + 255) / 256, 256>>>(x1g, W2, b2, out, N_PATH);
}

// round 12
// speedup vs baseline: 1.8934x; 1.0551x over previous
#include <cuda_runtime.h>
#include <cuda_bf16.h>
#include <cstdint>

// Problem dims
#define N_LINK 2000
#define N_FLOW 30000
#define N_PATH 50000
#define E1 120000
#define E2 120000
#define HID 256
#define NH 4
#define HD 256
#define HDTOT 1024

// ---------------- scratch ------------------------------------------------------
__device__ float g_hp1[N_PATH * HID];          // fp32 (needed for er2 dot)
__device__ float g_z1[N_LINK * HDTOT];
__device__ float g_z2[N_FLOW * HDTOT];
__device__ float g_aggm1[N_PATH * HID];        // conv1 agg, later reused as x1part
__device__ float g_aggm2[N_PATH * HID];
__device__ float g_x1[N_PATH * HID];
__device__ uint32_t g_hlinkp[N_LINK * HID];
__device__ uint32_t g_hflowp[N_FLOW * HID];
__device__ uint32_t g_hp0p[N_PATH * HID];
__device__ uint32_t g_hp1p[N_PATH * HID];
__device__ uint32_t g_hp2p[N_PATH * HID];
__device__ uint32_t g_fc1p[HID * HDTOT];
__device__ uint32_t g_fc2p[HID * HDTOT];
__device__ uint32_t g_rw1p[HID * HID];
__device__ uint32_t g_rw2p[HID * HID];
__device__ uint32_t g_w1sp[HID * HID];   // pack(W1a + W1c)
__device__ uint32_t g_w1bp[HID * HID];   // pack(W1b)
__device__ float g_vl1[HID * NH];
__device__ float g_vr1[HID * NH];
__device__ float g_vl2[HID * NH];
__device__ float g_vr2[HID * NH];
__device__ float g_ce[NH];
__device__ float g_el1[N_LINK * NH];
__device__ float g_er1[N_PATH * NH];
__device__ float g_el2[N_FLOW * NH];
__device__ float g_er2[N_PATH * NH];
__device__ float g_elog1[E1 * NH];
__device__ float g_elog2[E2 * NH];
__device__ float g_denom1[N_PATH * NH];
__device__ float g_denom2[N_PATH * NH];

// ---------------- packing ------------------------------------------------------
__device__ __forceinline__ uint32_t pack_split(float x) {
    __nv_bfloat16 h = __float2bfloat16_rn(x);
    float r = x - __bfloat162float(h);
    __nv_bfloat16 l = __float2bfloat16_rn(r);
    return ((uint32_t)__bfloat16_as_ushort(l) << 16) | (uint32_t)__bfloat16_as_ushort(h);
}

// one kernel packs all weight matrices (incl. the folded W1a+W1c)
#define PK0 (HID * HDTOT)             // fc_src1 -> fc1p
#define PK1 (PK0 + HID * HDTOT)       // fc_src2 -> fc2p
#define PK2 (PK1 + HID * HID)         // res_W1 -> rw1p
#define PK3 (PK2 + HID * HID)         // res_W2 -> rw2p
#define PK4 (PK3 + HID * HID)         // W1a+W1c -> w1sp
#define PKT (PK4 + HID * HID)         // W1b -> w1bp
__global__ void pack_all_kernel(const float* __restrict__ fc1, const float* __restrict__ fc2,
                                const float* __restrict__ rw1, const float* __restrict__ rw2,
                                const float* __restrict__ w1,
                                uint32_t* __restrict__ fc1p, uint32_t* __restrict__ fc2p,
                                uint32_t* __restrict__ rw1p, uint32_t* __restrict__ rw2p,
                                uint32_t* __restrict__ w1sp, uint32_t* __restrict__ w1bp) {
    int i = blockIdx.x * blockDim.x + threadIdx.x;
    if (i >= PKT) return;
    if (i < PK0) fc1p[i] = pack_split(fc1[i]);
    else if (i < PK1) fc2p[i - PK0] = pack_split(fc2[i - PK0]);
    else if (i < PK2) rw1p[i - PK1] = pack_split(rw1[i - PK1]);
    else if (i < PK3) rw2p[i - PK2] = pack_split(rw2[i - PK2]);
    else if (i < PK4) {
        int k = i - PK3;
        w1sp[k] = pack_split(w1[k] + w1[512 * HID + k]);
    } else {
        int k = i - PK4;
        w1bp[k] = pack_split(w1[256 * HID + k]);
    }
}

// batched attention-vector kernel
__global__ void attnvec_all_kernel(
    const float* f0, const float* a0, float* v0,
    const float* f1, const float* a1, float* v1,
    const float* f2, const float* a2, float* v2,
    const float* f3, const float* a3, float* v3,
    const float* f4, const float* a4, float* v4) {
    int y = blockIdx.y;
    const float* fc; const float* attn; float* v;
    switch (y) {
        case 0: fc = f0; attn = a0; v = v0; break;
        case 1: fc = f1; attn = a1; v = v1; break;
        case 2: fc = f2; attn = a2; v = v2; break;
        case 3: fc = f3; attn = a3; v = v3; break;
        default: fc = f4; attn = a4; v = v4; break;
    }
    int k = blockIdx.x;
    if (y == 4 && k > 0) return;
    int h = threadIdx.x >> 5;
    int lane = threadIdx.x & 31;
    float s = 0.f;
    const float* fr = fc + (size_t)k * HDTOT + h * HD;
    const float* ar = attn + h * HD;
    for (int d = lane; d < HD; d += 32) s = fmaf(fr[d], ar[d], s);
#pragma unroll
    for (int o = 16; o; o >>= 1) s += __shfl_xor_sync(0xffffffffu, s, o);
    if (lane == 0) v[k * NH + h] = s;
}

// row-tiled projection: 32 rows/block, warp partials to private smem slots,
// ONE barrier, then 128 threads combine all rows.
#define PROJ_R 32
template <int K>
__global__ __launch_bounds__(256) void proj_tiled(
    const float* __restrict__ x, const float* __restrict__ W,
    const float* __restrict__ b, uint32_t* __restrict__ outp,
    const float* __restrict__ vdot, float* __restrict__ eout, int N) {
    __shared__ float xs[PROJ_R][K];
    __shared__ float redm[PROJ_R][8][NH];   // 4 KB
    int n0 = blockIdx.x * PROJ_R;
    int j = threadIdx.x;
    float wreg[K];
#pragma unroll
    for (int k = 0; k < K; k++) wreg[k] = W[k * HID + j];
    float breg = b[j];
    float v0 = vdot[j * NH + 0], v1 = vdot[j * NH + 1];
    float v2 = vdot[j * NH + 2], v3 = vdot[j * NH + 3];
    for (int i = j; i < PROJ_R * K; i += 256) {
        int r = i / K, k = i % K;
        int n = n0 + r;
        xs[r][k] = (n < N) ? x[(size_t)n * K + k] : 0.f;
    }
    __syncthreads();
    int w = j >> 5, lane = j & 31;
    for (int r = 0; r < PROJ_R; r++) {
        int n = n0 + r;
        if (n >= N) break;  // uniform across block
        float acc = breg;
#pragma unroll
        for (int k = 0; k < K; k++) acc = fmaf(xs[r][k], wreg[k], acc);
        acc = fmaxf(acc, 0.0f);
        outp[(size_t)n * HID + j] = pack_split(acc);
        float p0 = acc * v0, p1 = acc * v1, p2 = acc * v2, p3 = acc * v3;
#pragma unroll
        for (int o = 16; o; o >>= 1) {
            p0 += __shfl_xor_sync(0xffffffffu, p0, o);
            p1 += __shfl_xor_sync(0xffffffffu, p1, o);
            p2 += __shfl_xor_sync(0xffffffffu, p2, o);
            p3 += __shfl_xor_sync(0xffffffffu, p3, o);
        }
        if (lane == 0) {
            redm[r][w][0] = p0; redm[r][w][1] = p1;
            redm[r][w][2] = p2; redm[r][w][3] = p3;
        }
    }
    __syncthreads();
    if (j < PROJ_R * NH) {
        int r = j >> 2, h = j & 3;
        int n = n0 + r;
        if (n < N) {
            float s = 0.f;
#pragma unroll
            for (int ww = 0; ww < 8; ww++) s += redm[r][ww][h];
            eout[(size_t)n * NH + h] = s;
        }
    }
}

// er2 = hp1 @ vr2
__global__ void dotvec_kernel(const float* __restrict__ hsrc, const float* __restrict__ v,
                              float* __restrict__ out, int N) {
    int n = blockIdx.x;
    if (n >= N) return;
    int h = threadIdx.x >> 5;
    int lane = threadIdx.x & 31;
    const float* hr = hsrc + (size_t)n * HID;
    float s = 0.f;
    for (int k = lane; k < HID; k += 32) s = fmaf(hr[k], v[k * NH + h], s);
#pragma unroll
    for (int o = 16; o; o >>= 1) s += __shfl_xor_sync(0xffffffffu, s, o);
    if (lane == 0) out[n * NH + h] = s;
}

// fused softmax numerator + denominator (max-shift dropped: logits O(0.1))
__global__ void edge_softmax_kernel(const int* __restrict__ src, const int* __restrict__ dst,
                                    const float* __restrict__ el, const float* __restrict__ er,
                                    const float* __restrict__ e2p, const float* __restrict__ ce,
                                    float* __restrict__ elog, float* __restrict__ denom,
                                    int E, int use_ee) {
    int i = blockIdx.x * blockDim.x + threadIdx.x;
    if (i >= E * NH) return;
    int e = i >> 2, h = i & 3;
    int s = src[e], t = dst[e];
    float v = el[s * NH + h] + er[t * NH + h];
    if (use_ee) v = fmaf(e2p[e], ce[h], v);
    v = (v > 0.f) ? v : 0.2f * v;
    float a = expf(v);
    elog[i] = a;
    atomicAdd(&denom[t * NH + h], a);
}

// aggregate (head mean fused), 4 edges per 256-thread block
__global__ void aggregate_kernel(const int* __restrict__ src, const int* __restrict__ dst,
                                 const float* __restrict__ anum, const float* __restrict__ denom,
                                 const float* __restrict__ z, float* __restrict__ aggm, int E) {
    __shared__ float al[4][NH];
    __shared__ int sidx[4], tidx[4];
    int e0 = blockIdx.x * 4;
    int tid = threadIdx.x;
    if (tid < 16) {
        int le = tid >> 2, h = tid & 3;
        int e = e0 + le;
        if (e < E) {
            int t = dst[e];
            float dn = denom[t * NH + h];
            al[le][h] = anum[e * NH + h] / fmaxf(dn, 1e-9f) * 0.25f;
            if (h == 0) { sidx[le] = src[e]; tidx[le] = t; }
        }
    }
    __syncthreads();
    int le = tid >> 6, t64 = tid & 63;
    int e = e0 + le;
    if (e >= E) return;
    int s = sidx[le], t = tidx[le];
    const float4* zr = (const float4*)(z + (size_t)s * HDTOT);
    float4 v = make_float4(0.f, 0.f, 0.f, 0.f);
#pragma unroll
    for (int h = 0; h < NH; h++) {
        float a = al[le][h];
        float4 zv = zr[h * 64 + t64];
        v.x = fmaf(a, zv.x, v.x);
        v.y = fmaf(a, zv.y, v.y);
        v.z = fmaf(a, zv.z, v.z);
        v.w = fmaf(a, zv.w, v.w);
    }
    float* p = aggm + (size_t)t * HID + t64 * 4;
    asm volatile("red.global.add.v4.f32 [%0], {%1,%2,%3,%4};"
                 :: "l"(p), "f"(v.x), "f"(v.y), "f"(v.z), "f"(v.w) : "memory");
}

// ---------------- dual-bf16 GEMM with paired-lo (3 mmas / 16 real k) -----------
#define FLAG_RELU 1
#define STAGES 2

__device__ __forceinline__ void mma_bf16(float* c, const uint32_t* a, const uint32_t* b) {
    asm volatile(
        "mma.sync.aligned.m16n8k16.row.col.f32.bf16.bf16.f32 "
        "{%0,%1,%2,%3}, {%4,%5,%6,%7}, {%8,%9}, {%0,%1,%2,%3};"
        : "+f"(c[0]), "+f"(c[1]), "+f"(c[2]), "+f"(c[3])
        : "r"(a[0]), "r"(a[1]), "r"(a[2]), "r"(a[3]), "r"(b[0]), "r"(b[1]));
}

__global__ __launch_bounds__(256) void gemm_db16(
    const uint32_t* __restrict__ A0, const uint32_t* __restrict__ A1p, const uint32_t* __restrict__ A2p,
    const uint32_t* __restrict__ B, float* __restrict__ C, uint32_t* __restrict__ Cp,
    int M, int N, int nseg,
    const float* __restrict__ addv, const float* __restrict__ bias, int flags) {
    __shared__ uint32_t As[STAGES][128][20];
    __shared__ uint32_t Bs[STAGES][16][136];

    int bm = blockIdx.y * 128, bn = blockIdx.x * 128;
    int tid = threadIdx.x;
    int w = tid >> 5, lane = tid & 31;
    int gid = lane >> 2, tig = lane & 3;
    int wm = (w >> 2) * 64, wn = (w & 3) * 32;

    int Ktot = nseg << 8;
    int ntile = Ktot >> 4;

    auto load_tile = [&](int slot, int t) {
        int k0 = t << 4;
        const uint32_t* A = (k0 < 256) ? A0 : (k0 < 512 ? A1p : A2p);
        int kk = k0 & 255;
#pragma unroll
        for (int it = 0; it < 2; it++) {
            int idx = tid + it * 256;
            int row = idx >> 2, qc = (idx & 3) * 4;
            int gr = bm + row;
            int grc = gr < M ? gr : 0;
            const uint32_t* g = A + (size_t)grc * 256 + kk + qc;
            uint32_t sa = (uint32_t)__cvta_generic_to_shared(&As[slot][row][qc]);
            asm volatile("cp.async.cg.shared.global [%0], [%1], 16, %2;"
                         :: "r"(sa), "l"(g), "r"(gr < M ? 16 : 0) : "memory");
            int brow = idx >> 5, nc = (idx & 31) * 4;
            const uint32_t* gB = B + (size_t)(k0 + brow) * N + bn + nc;
            uint32_t sb = (uint32_t)__cvta_generic_to_shared(&Bs[slot][brow][nc]);
            asm volatile("cp.async.cg.shared.global [%0], [%1], 16, 16;"
                         :: "r"(sb), "l"(gB) : "memory");
        }
    };

    float acc[4][4][4];
#pragma unroll
    for (int i = 0; i < 4; i++)
#pragma unroll
        for (int j = 0; j < 4; j++)
#pragma unroll
            for (int q = 0; q < 4; q++) acc[i][j][q] = 0.f;

    load_tile(0, 0);
    asm volatile("cp.async.commit_group;" ::: "memory");

    for (int t = 0; t < ntile; t++) {
        asm volatile("cp.async.wait_group 0;" ::: "memory");
        __syncthreads();
        int nt = t + 1;
        if (nt < ntile) {
            load_tile(nt & 1, nt);
            asm volatile("cp.async.commit_group;" ::: "memory");
        }
        int sl = t & 1;
        uint32_t b1a[4][2], b1b[4][2], b2f[4][2];
#pragma unroll
        for (int j = 0; j < 4; j++) {
            int c0 = wn + 8 * j + gid;
            uint32_t w00 = Bs[sl][tig][c0];
            uint32_t w01 = Bs[sl][tig + 4][c0];
            uint32_t w10 = Bs[sl][tig + 8][c0];
            uint32_t w11 = Bs[sl][tig + 12][c0];
            b1a[j][0] = __byte_perm(w00, w00, 0x1010);
            b1a[j][1] = __byte_perm(w01, w01, 0x1010);
            b1b[j][0] = __byte_perm(w10, w10, 0x1010);
            b1b[j][1] = __byte_perm(w11, w11, 0x1010);
            b2f[j][0] = __byte_perm(w00, w10, 0x7632);
            b2f[j][1] = __byte_perm(w01, w11, 0x7632);
        }
#pragma unroll
        for (int i = 0; i < 4; i++) {
            int r0 = wm + 16 * i + gid;
            uint32_t u00 = As[sl][r0][tig];
            uint32_t u01 = As[sl][r0][tig + 4];
            uint32_t u02 = As[sl][r0][tig + 8];
            uint32_t u03 = As[sl][r0][tig + 12];
            uint32_t u10 = As[sl][r0 + 8][tig];
            uint32_t u11 = As[sl][r0 + 8][tig + 4];
            uint32_t u12 = As[sl][r0 + 8][tig + 8];
            uint32_t u13 = As[sl][r0 + 8][tig + 12];
            uint32_t a1a[4] = {u00, u10, u01, u11};
            uint32_t a1b[4] = {u02, u12, u03, u13};
            uint32_t a2[4] = {__byte_perm(u00, u02, 0x5410), __byte_perm(u10, u12, 0x5410),
                              __byte_perm(u01, u03, 0x5410), __byte_perm(u11, u13, 0x5410)};
#pragma unroll
            for (int j = 0; j < 4; j++) {
                mma_bf16(acc[i][j], a1a, b1a[j]);
                mma_bf16(acc[i][j], a1b, b1b[j]);
                mma_bf16(acc[i][j], a2, b2f[j]);
            }
        }
        __syncthreads();
    }

#pragma unroll
    for (int i = 0; i < 4; i++) {
#pragma unroll
        for (int j = 0; j < 4; j++) {
            int r0 = bm + wm + 16 * i + gid;
            int r1 = r0 + 8;
            int c = bn + wn + 8 * j + 2 * tig;
            float2 v0 = make_float2(acc[i][j][0], acc[i][j][1]);
            float2 v1 = make_float2(acc[i][j][2], acc[i][j][3]);
            float bx = 0.f, by = 0.f;
            if (bias) { bx = bias[c]; by = bias[c + 1]; }
            if (r0 < M) {
                size_t idx = (size_t)r0 * N + c;
                if (addv) { v0.x += addv[idx]; v0.y += addv[idx + 1]; }
                v0.x += bx; v0.y += by;
                if (flags & FLAG_RELU) { v0.x = fmaxf(v0.x, 0.f); v0.y = fmaxf(v0.y, 0.f); }
                if (C) *(float2*)(C + idx) = v0;
                if (Cp) { Cp[idx] = pack_split(v0.x); Cp[idx + 1] = pack_split(v0.y); }
            }
            if (r1 < M) {
                size_t idx = (size_t)r1 * N + c;
                if (addv) { v1.x += addv[idx]; v1.y += addv[idx + 1]; }
                v1.x += bx; v1.y += by;
                if (flags & FLAG_RELU) { v1.x = fmaxf(v1.x, 0.f); v1.y = fmaxf(v1.y, 0.f); }
                if (C) *(float2*)(C + idx) = v1;
                if (Cp) { Cp[idx] = pack_split(v1.x); Cp[idx + 1] = pack_split(v1.y); }
            }
        }
    }
}

// final: out[n,0:2] = x1[n,:]@W2[256,2] + b2
__global__ void final_kernel(const float* __restrict__ x1, const float* __restrict__ W2,
                             const float* __restrict__ b2, float* __restrict__ out, int N) {
    int warp = (blockIdx.x * blockDim.x + threadIdx.x) >> 5;
    int lane = threadIdx.x & 31;
    if (warp >= N) return;
    const float* xr = x1 + (size_t)warp * HID;
    float s0 = 0.f, s1 = 0.f;
    for (int k = lane; k < HID; k += 32) {
        float xv = xr[k];
        s0 = fmaf(xv, W2[k * 2 + 0], s0);
        s1 = fmaf(xv, W2[k * 2 + 1], s1);
    }
#pragma unroll
    for (int o = 16; o; o >>= 1) {
        s0 += __shfl_xor_sync(0xffffffffu, s0, o);
        s1 += __shfl_xor_sync(0xffffffffu, s1, o);
    }
    if (lane == 0) {
        out[warp * 2 + 0] = s0 + b2[0];
        out[warp * 2 + 1] = s1 + b2[1];
    }
}

// ---------------- host launcher -------------------------------------------------
static inline void* sym(const void* s) {
    void* p = nullptr;
    cudaGetSymbolAddress(&p, s);
    return p;
}

extern "C" void kernel_launch(void* const* d_in, const int* in_sizes, int n_in,
                              void* d_out, int out_size) {
    const float* x_link = (const float*)d_in[0];
    const float* x_flow = (const float*)d_in[1];
    const float* x_path = (const float*)d_in[2];
    const float* e2p = (const float*)d_in[3];
    const float* Wp_link = (const float*)d_in[4];
    const float* bp_link = (const float*)d_in[5];
    const float* Wp_flow = (const float*)d_in[6];
    const float* bp_flow = (const float*)d_in[7];
    const float* Wp_path = (const float*)d_in[8];
    const float* bp_path = (const float*)d_in[9];
    const float* fc_src1 = (const float*)d_in[10];
    const float* fc_dst1 = (const float*)d_in[11];
    const float* fc_e1 = (const float*)d_in[12];
    const float* attn_l1 = (const float*)d_in[13];
    const float* attn_r1 = (const float*)d_in[14];
    const float* attn_e1 = (const float*)d_in[15];
    const float* res_W1 = (const float*)d_in[16];
    const float* fc_src2 = (const float*)d_in[17];
    const float* fc_dst2 = (const float*)d_in[18];
    const float* attn_l2 = (const float*)d_in[19];
    const float* attn_r2 = (const float*)d_in[20];
    const float* res_W2 = (const float*)d_in[21];
    const float* W1 = (const float*)d_in[22];
    const float* b1 = (const float*)d_in[23];
    const float* W2 = (const float*)d_in[24];
    const float* b2 = (const float*)d_in[25];
    const int* src1 = (const int*)d_in[26];
    const int* dst1 = (const int*)d_in[27];
    const int* src2 = (const int*)d_in[28];
    const int* dst2 = (const int*)d_in[29];
    float* out = (float*)d_out;

    float* hp1 = (float*)sym(g_hp1);
    float* z1 = (float*)sym(g_z1);
    float* z2 = (float*)sym(g_z2);
    float* aggm1 = (float*)sym(g_aggm1);
    float* aggm2 = (float*)sym(g_aggm2);
    float* x1g = (float*)sym(g_x1);
    uint32_t* hlinkp = (uint32_t*)sym(g_hlinkp);
    uint32_t* hflowp = (uint32_t*)sym(g_hflowp);
    uint32_t* hp0p = (uint32_t*)sym(g_hp0p);
    uint32_t* hp1p = (uint32_t*)sym(g_hp1p);
    uint32_t* hp2p = (uint32_t*)sym(g_hp2p);
    uint32_t* fc1p = (uint32_t*)sym(g_fc1p);
    uint32_t* fc2p = (uint32_t*)sym(g_fc2p);
    uint32_t* rw1p = (uint32_t*)sym(g_rw1p);
    uint32_t* rw2p = (uint32_t*)sym(g_rw2p);
    uint32_t* w1sp = (uint32_t*)sym(g_w1sp);
    uint32_t* w1bp = (uint32_t*)sym(g_w1bp);
    float* vl1 = (float*)sym(g_vl1);
    float* vr1 = (float*)sym(g_vr1);
    float* vl2 = (float*)sym(g_vl2);
    float* vr2 = (float*)sym(g_vr2);
    float* ce = (float*)sym(g_ce);
    float* el1 = (float*)sym(g_el1);
    float* er1 = (float*)sym(g_er1);
    float* el2 = (float*)sym(g_el2);
    float* er2 = (float*)sym(g_er2);
    float* elog1 = (float*)sym(g_elog1);
    float* elog2 = (float*)sym(g_elog2);
    float* denom1 = (float*)sym(g_denom1);
    float* denom2 = (float*)sym(g_denom2);

    cudaStream_t sB;
    cudaStreamCreateWithFlags(&sB, cudaStreamNonBlocking);
    cudaEvent_t evFork, evEr2, evX1p;
    cudaEventCreateWithFlags(&evFork, cudaEventDisableTiming);
    cudaEventCreateWithFlags(&evEr2, cudaEventDisableTiming);
    cudaEventCreateWithFlags(&evX1p, cudaEventDisableTiming);

    dim3 gz1(HDTOT / 128, (N_LINK + 127) / 128);
    dim3 gz2(HDTOT / 128, (N_FLOW + 127) / 128);
    dim3 gres(HID / 128, (N_PATH + 127) / 128);

    // ---------- shared prologue (main stream) ----------
    attnvec_all_kernel<<<dim3(HID, 5), 128>>>(
        fc_src1, attn_l1, vl1, fc_dst1, attn_r1, vr1,
        fc_src2, attn_l2, vl2, fc_dst2, attn_r2, vr2,
        fc_e1, attn_e1, ce);
    pack_all_kernel<<<(PKT + 255) / 256, 256>>>(fc_src1, fc_src2, res_W1, res_W2, W1,
                                                fc1p, fc2p, rw1p, rw2p, w1sp, w1bp);
    cudaMemsetAsync(denom1, 0, (size_t)N_PATH * NH * sizeof(float));
    cudaMemsetAsync(aggm1, 0, (size_t)N_PATH * HID * sizeof(float));
    cudaMemsetAsync(denom2, 0, (size_t)N_PATH * NH * sizeof(float));
    cudaMemsetAsync(aggm2, 0, (size_t)N_PATH * HID * sizeof(float));

    // ---------- fork: stream B runs the full conv1 chain + decoder partial ----------
    cudaEventRecord(evFork, 0);
    cudaStreamWaitEvent(sB, evFork, 0);

    proj_tiled<8><<<(N_LINK + PROJ_R - 1) / PROJ_R, 256, 0, sB>>>(
        x_link, Wp_link, bp_link, hlinkp, vl1, el1, N_LINK);
    proj_tiled<8><<<(N_PATH + PROJ_R - 1) / PROJ_R, 256, 0, sB>>>(
        x_path, Wp_path, bp_path, hp0p, vr1, er1, N_PATH);
    gemm_db16<<<gz1, 256, 0, sB>>>(hlinkp, nullptr, nullptr, fc1p, z1, nullptr,
                                   N_LINK, HDTOT, 1, nullptr, nullptr, 0);
    edge_softmax_kernel<<<(E1 * NH + 255) / 256, 256, 0, sB>>>(
        src1, dst1, el1, er1, e2p, ce, elog1, denom1, E1, 1);
    aggregate_kernel<<<(E1 + 3) / 4, 256, 0, sB>>>(src1, dst1, elog1, denom1, z1, aggm1, E1);
    gemm_db16<<<gres, 256, 0, sB>>>(hp0p, nullptr, nullptr, rw1p, hp1, hp1p,
                                    N_PATH, HID, 1, aggm1, nullptr, FLAG_RELU);
    dotvec_kernel<<<N_PATH, 128, 0, sB>>>(hp1, vr2, er2, N_PATH);
    cudaEventRecord(evEr2, sB);
    // decoder partial: x1part (into retired aggm1) = hp1 @ W1b — overlaps conv2 on main
    gemm_db16<<<gres, 256, 0, sB>>>(hp1p, nullptr, nullptr, w1bp, aggm1, nullptr,
                                    N_PATH, HID, 1, nullptr, nullptr, 0);
    cudaEventRecord(evX1p, sB);

    // ---------- main stream: flow proj + big z2 GEMM ----------
    proj_tiled<16><<<(N_FLOW + PROJ_R - 1) / PROJ_R, 256>>>(
        x_flow, Wp_flow, bp_flow, hflowp, vl2, el2, N_FLOW);
    gemm_db16<<<gz2, 256>>>(hflowp, nullptr, nullptr, fc2p, z2, nullptr,
                            N_FLOW, HDTOT, 1, nullptr, nullptr, 0);

    // ---------- join for er2, then conv2 ----------
    cudaStreamWaitEvent(0, evEr2, 0);

    edge_softmax_kernel<<<(E2 * NH + 255) / 256, 256>>>(
        src2, dst2, el2, er2, nullptr, ce, elog2, denom2, E2, 0);
    aggregate_kernel<<<(E2 + 3) / 4, 256>>>(src2, dst2, elog2, denom2, z2, aggm2, E2);

    gemm_db16<<<gres, 256>>>(hp1p, nullptr, nullptr, rw2p, nullptr, hp2p,
                             N_PATH, HID, 1, aggm2, nullptr, FLAG_RELU);

    // ---------- decoder: x1 = relu(hp2@(W1a+W1c) + x1part + b1) ----------
    cudaStreamWaitEvent(0, evX1p, 0);
    gemm_db16<<<gres, 256>>>(hp2p, nullptr, nullptr, w1sp, x1g, nullptr,
                             N_PATH, HID, 1, aggm1, b1, FLAG_RELU);

    final_kernel<<<(N_PATH * 32 + 255) / 256, 256>>>(x1g, W2, b2, out, N_PATH);
}

// round 15
// speedup vs baseline: 1.9720x; 1.0415x over previous
#include <cuda_runtime.h>
#include <cuda_bf16.h>
#include <cstdint>

// Problem dims
#define N_LINK 2000
#define N_FLOW 30000
#define N_PATH 50000
#define E1 120000
#define E2 120000
#define HID 256
#define NH 4
#define HD 256
#define HDTOT 1024

// ---------------- scratch ------------------------------------------------------
__device__ float g_z1[N_LINK * HDTOT];
__device__ float g_z2[N_FLOW * HDTOT];
__device__ float g_aggm1[N_PATH * HID];        // conv1 agg, later reused as x1part
__device__ float g_aggm2[N_PATH * HID];
__device__ float g_x1[N_PATH * HID];
__device__ uint32_t g_hlinkp[N_LINK * HID];
__device__ uint32_t g_hflowp[N_FLOW * HID];
__device__ uint32_t g_hp0p[N_PATH * HID];
__device__ uint32_t g_hp1p[N_PATH * HID];
__device__ uint32_t g_hp2p[N_PATH * HID];
__device__ uint32_t g_fc1p[HID * HDTOT];
__device__ uint32_t g_fc2p[HID * HDTOT];
__device__ uint32_t g_rw1p[HID * HID];
__device__ uint32_t g_rw2p[HID * HID];
__device__ uint32_t g_w1sp[HID * HID];   // pack(W1a + W1c)
__device__ uint32_t g_w1bp[HID * HID];   // pack(W1b)
__device__ float g_vl1[HID * NH];
__device__ float g_vr1[HID * NH];
__device__ float g_vl2[HID * NH];
__device__ float g_vr2[HID * NH];
__device__ float g_ce[NH];
__device__ float g_el1[N_LINK * NH];
__device__ float g_er1[N_PATH * NH];
__device__ float g_el2[N_FLOW * NH];
__device__ float g_er2[N_PATH * NH];
__device__ float g_elog1[E1 * NH];
__device__ float g_elog2[E2 * NH];
__device__ float g_denom1[N_PATH * NH];
__device__ float g_denom2[N_PATH * NH];

// ---------------- packing ------------------------------------------------------
__device__ __forceinline__ uint32_t pack_split(float x) {
    __nv_bfloat16 h = __float2bfloat16_rn(x);
    float r = x - __bfloat162float(h);
    __nv_bfloat16 l = __float2bfloat16_rn(r);
    return ((uint32_t)__bfloat16_as_ushort(l) << 16) | (uint32_t)__bfloat16_as_ushort(h);
}
__device__ __forceinline__ float unpack_split(uint32_t w) {
    __nv_bfloat16 h = __ushort_as_bfloat16((unsigned short)(w & 0xFFFFu));
    __nv_bfloat16 l = __ushort_as_bfloat16((unsigned short)(w >> 16));
    return __bfloat162float(h) + __bfloat162float(l);
}

// one kernel packs all weight matrices (incl. the folded W1a+W1c)
#define PK0 (HID * HDTOT)
#define PK1 (PK0 + HID * HDTOT)
#define PK2 (PK1 + HID * HID)
#define PK3 (PK2 + HID * HID)
#define PK4 (PK3 + HID * HID)
#define PKT (PK4 + HID * HID)
__global__ void pack_all_kernel(const float* __restrict__ fc1, const float* __restrict__ fc2,
                                const float* __restrict__ rw1, const float* __restrict__ rw2,
                                const float* __restrict__ w1,
                                uint32_t* __restrict__ fc1p, uint32_t* __restrict__ fc2p,
                                uint32_t* __restrict__ rw1p, uint32_t* __restrict__ rw2p,
                                uint32_t* __restrict__ w1sp, uint32_t* __restrict__ w1bp) {
    int i = blockIdx.x * blockDim.x + threadIdx.x;
    if (i >= PKT) return;
    if (i < PK0) fc1p[i] = pack_split(fc1[i]);
    else if (i < PK1) fc2p[i - PK0] = pack_split(fc2[i - PK0]);
    else if (i < PK2) rw1p[i - PK1] = pack_split(rw1[i - PK1]);
    else if (i < PK3) rw2p[i - PK2] = pack_split(rw2[i - PK2]);
    else if (i < PK4) {
        int k = i - PK3;
        w1sp[k] = pack_split(w1[k] + w1[512 * HID + k]);
    } else {
        int k = i - PK4;
        w1bp[k] = pack_split(w1[256 * HID + k]);
    }
}

// batched attention-vector kernel
__global__ void attnvec_all_kernel(
    const float* f0, const float* a0, float* v0,
    const float* f1, const float* a1, float* v1,
    const float* f2, const float* a2, float* v2,
    const float* f3, const float* a3, float* v3,
    const float* f4, const float* a4, float* v4) {
    int y = blockIdx.y;
    const float* fc; const float* attn; float* v;
    switch (y) {
        case 0: fc = f0; attn = a0; v = v0; break;
        case 1: fc = f1; attn = a1; v = v1; break;
        case 2: fc = f2; attn = a2; v = v2; break;
        case 3: fc = f3; attn = a3; v = v3; break;
        default: fc = f4; attn = a4; v = v4; break;
    }
    int k = blockIdx.x;
    if (y == 4 && k > 0) return;
    int h = threadIdx.x >> 5;
    int lane = threadIdx.x & 31;
    float s = 0.f;
    const float* fr = fc + (size_t)k * HDTOT + h * HD;
    const float* ar = attn + h * HD;
    for (int d = lane; d < HD; d += 32) s = fmaf(fr[d], ar[d], s);
#pragma unroll
    for (int o = 16; o; o >>= 1) s += __shfl_xor_sync(0xffffffffu, s, o);
    if (lane == 0) v[k * NH + h] = s;
}

// row-tiled projection with 6-shfl transpose-reduction for the fused dot.
#define PROJ_R 32
template <int K>
__global__ __launch_bounds__(256) void proj_tiled(
    const float* __restrict__ x, const float* __restrict__ W,
    const float* __restrict__ b, uint32_t* __restrict__ outp,
    const float* __restrict__ vdot, float* __restrict__ eout, int N) {
    __shared__ float xs[PROJ_R][K];
    __shared__ float redm[PROJ_R][8][NH];
    int n0 = blockIdx.x * PROJ_R;
    int j = threadIdx.x;
    float wreg[K];
#pragma unroll
    for (int k = 0; k < K; k++) wreg[k] = W[k * HID + j];
    float breg = b[j];
    float v0 = vdot[j * NH + 0], v1 = vdot[j * NH + 1];
    float v2 = vdot[j * NH + 2], v3 = vdot[j * NH + 3];
    for (int i = j; i < PROJ_R * K; i += 256) {
        int r = i / K, k = i % K;
        int n = n0 + r;
        xs[r][k] = (n < N) ? x[(size_t)n * K + k] : 0.f;
    }
    __syncthreads();
    int w = j >> 5, lane = j & 31;
    int b0 = lane & 1, b1 = lane & 2;
    for (int r = 0; r < PROJ_R; r++) {
        int n = n0 + r;
        if (n >= N) break;  // uniform across block
        float acc = breg;
#pragma unroll
        for (int k = 0; k < K; k++) acc = fmaf(xs[r][k], wreg[k], acc);
        acc = fmaxf(acc, 0.0f);
        outp[(size_t)n * HID + j] = pack_split(acc);
        float p0 = acc * v0, p1 = acc * v1, p2 = acc * v2, p3 = acc * v3;
        // stage 1 (offset 1): value-identity exchange
        float rA = __shfl_xor_sync(0xffffffffu, b0 ? p0 : p1, 1);
        float qa = (b0 ? p1 : p0) + rA;       // value idx = lane&1
        float rB = __shfl_xor_sync(0xffffffffu, b0 ? p2 : p3, 1);
        float qb = (b0 ? p3 : p2) + rB;       // value idx = 2+(lane&1)
        // stage 2 (offset 2)
        float rC = __shfl_xor_sync(0xffffffffu, b1 ? qa : qb, 2);
        float rr = (b1 ? qb : qa) + rC;       // value idx = lane&3
        // stages 3-5: plain reduce across mod-4 classes
        rr += __shfl_xor_sync(0xffffffffu, rr, 4);
        rr += __shfl_xor_sync(0xffffffffu, rr, 8);
        rr += __shfl_xor_sync(0xffffffffu, rr, 16);
        if (lane < NH) redm[r][w][lane] = rr;  // lane == value idx
    }
    __syncthreads();
    if (j < PROJ_R * NH) {
        int r = j >> 2, h = j & 3;
        int n = n0 + r;
        if (n < N) {
            float s = 0.f;
#pragma unroll
            for (int ww = 0; ww < 8; ww++) s += redm[r][ww][h];
            eout[(size_t)n * NH + h] = s;
        }
    }
}

// er2 = hp1 @ vr2, reading packed (hi,lo) words
__global__ void dotvec_packed_kernel(const uint32_t* __restrict__ hsrcp, const float* __restrict__ v,
                                     float* __restrict__ out, int N) {
    int n = blockIdx.x;
    if (n >= N) return;
    int h = threadIdx.x >> 5;
    int lane = threadIdx.x & 31;
    const uint32_t* hr = hsrcp + (size_t)n * HID;
    float s = 0.f;
    for (int k = lane; k < HID; k += 32) s = fmaf(unpack_split(hr[k]), v[k * NH + h], s);
#pragma unroll
    for (int o = 16; o; o >>= 1) s += __shfl_xor_sync(0xffffffffu, s, o);
    if (lane == 0) out[n * NH + h] = s;
}

// fused softmax numerator + denominator (max-shift dropped: logits O(0.1))
__global__ void edge_softmax_kernel(const int* __restrict__ src, const int* __restrict__ dst,
                                    const float* __restrict__ el, const float* __restrict__ er,
                                    const float* __restrict__ e2p, const float* __restrict__ ce,
                                    float* __restrict__ elog, float* __restrict__ denom,
                                    int E, int use_ee) {
    int i = blockIdx.x * blockDim.x + threadIdx.x;
    if (i >= E * NH) return;
    int e = i >> 2, h = i & 3;
    int s = src[e], t = dst[e];
    float v = el[s * NH + h] + er[t * NH + h];
    if (use_ee) v = fmaf(e2p[e], ce[h], v);
    v = (v > 0.f) ? v : 0.2f * v;
    float a = expf(v);
    elog[i] = a;
    atomicAdd(&denom[t * NH + h], a);
}

// aggregate (head mean fused), 4 edges per 256-thread block
__global__ void aggregate_kernel(const int* __restrict__ src, const int* __restrict__ dst,
                                 const float* __restrict__ anum, const float* __restrict__ denom,
                                 const float* __restrict__ z, float* __restrict__ aggm, int E) {
    __shared__ float al[4][NH];
    __shared__ int sidx[4], tidx[4];
    int e0 = blockIdx.x * 4;
    int tid = threadIdx.x;
    if (tid < 16) {
        int le = tid >> 2, h = tid & 3;
        int e = e0 + le;
        if (e < E) {
            int t = dst[e];
            float dn = denom[t * NH + h];
            al[le][h] = anum[e * NH + h] / fmaxf(dn, 1e-9f) * 0.25f;
            if (h == 0) { sidx[le] = src[e]; tidx[le] = t; }
        }
    }
    __syncthreads();
    int le = tid >> 6, t64 = tid & 63;
    int e = e0 + le;
    if (e >= E) return;
    int s = sidx[le], t = tidx[le];
    const float4* zr = (const float4*)(z + (size_t)s * HDTOT);
    float4 v = make_float4(0.f, 0.f, 0.f, 0.f);
#pragma unroll
    for (int h = 0; h < NH; h++) {
        float a = al[le][h];
        float4 zv = zr[h * 64 + t64];
        v.x = fmaf(a, zv.x, v.x);
        v.y = fmaf(a, zv.y, v.y);
        v.z = fmaf(a, zv.z, v.z);
        v.w = fmaf(a, zv.w, v.w);
    }
    float* p = aggm + (size_t)t * HID + t64 * 4;
    asm volatile("red.global.add.v4.f32 [%0], {%1,%2,%3,%4};"
                 :: "l"(p), "f"(v.x), "f"(v.y), "f"(v.z), "f"(v.w) : "memory");
}

// ---------------- dual-bf16 GEMM with paired-lo (3 mmas / 16 real k) -----------
#define FLAG_RELU 1
#define STAGES 2

__device__ __forceinline__ void mma_bf16(float* c, const uint32_t* a, const uint32_t* b) {
    asm volatile(
        "mma.sync.aligned.m16n8k16.row.col.f32.bf16.bf16.f32 "
        "{%0,%1,%2,%3}, {%4,%5,%6,%7}, {%8,%9}, {%0,%1,%2,%3};"
        : "+f"(c[0]), "+f"(c[1]), "+f"(c[2]), "+f"(c[3])
        : "r"(a[0]), "r"(a[1]), "r"(a[2]), "r"(a[3]), "r"(b[0]), "r"(b[1]));
}

__global__ __launch_bounds__(256) void gemm_db16(
    const uint32_t* __restrict__ A0, const uint32_t* __restrict__ A1p, const uint32_t* __restrict__ A2p,
    const uint32_t* __restrict__ B, float* __restrict__ C, uint32_t* __restrict__ Cp,
    int M, int N, int nseg,
    const float* __restrict__ addv, const float* __restrict__ bias, int flags) {
    __shared__ uint32_t As[STAGES][128][20];
    __shared__ uint32_t Bs[STAGES][16][136];

    int bm = blockIdx.y * 128, bn = blockIdx.x * 128;
    int tid = threadIdx.x;
    int w = tid >> 5, lane = tid & 31;
    int gid = lane >> 2, tig = lane & 3;
    int wm = (w >> 2) * 64, wn = (w & 3) * 32;

    int Ktot = nseg << 8;
    int ntile = Ktot >> 4;

    auto load_tile = [&](int slot, int t) {
        int k0 = t << 4;
        const uint32_t* A = (k0 < 256) ? A0 : (k0 < 512 ? A1p : A2p);
        int kk = k0 & 255;
#pragma unroll
        for (int it = 0; it < 2; it++) {
            int idx = tid + it * 256;
            int row = idx >> 2, qc = (idx & 3) * 4;
            int gr = bm + row;
            int grc = gr < M ? gr : 0;
            const uint32_t* g = A + (size_t)grc * 256 + kk + qc;
            uint32_t sa = (uint32_t)__cvta_generic_to_shared(&As[slot][row][qc]);
            asm volatile("cp.async.cg.shared.global [%0], [%1], 16, %2;"
                         :: "r"(sa), "l"(g), "r"(gr < M ? 16 : 0) : "memory");
            int brow = idx >> 5, nc = (idx & 31) * 4;
            const uint32_t* gB = B + (size_t)(k0 + brow) * N + bn + nc;
            uint32_t sb = (uint32_t)__cvta_generic_to_shared(&Bs[slot][brow][nc]);
            asm volatile("cp.async.cg.shared.global [%0], [%1], 16, 16;"
                         :: "r"(sb), "l"(gB) : "memory");
        }
    };

    float acc[4][4][4];
#pragma unroll
    for (int i = 0; i < 4; i++)
#pragma unroll
        for (int j = 0; j < 4; j++)
#pragma unroll
            for (int q = 0; q < 4; q++) acc[i][j][q] = 0.f;

    load_tile(0, 0);
    asm volatile("cp.async.commit_group;" ::: "memory");

    for (int t = 0; t < ntile; t++) {
        asm volatile("cp.async.wait_group 0;" ::: "memory");
        __syncthreads();
        int nt = t + 1;
        if (nt < ntile) {
            load_tile(nt & 1, nt);
            asm volatile("cp.async.commit_group;" ::: "memory");
        }
        int sl = t & 1;
        uint32_t b1a[4][2], b1b[4][2], b2f[4][2];
#pragma unroll
        for (int j = 0; j < 4; j++) {
            int c0 = wn + 8 * j + gid;
            uint32_t w00 = Bs[sl][tig][c0];
            uint32_t w01 = Bs[sl][tig + 4][c0];
            uint32_t w10 = Bs[sl][tig + 8][c0];
            uint32_t w11 = Bs[sl][tig + 12][c0];
            b1a[j][0] = __byte_perm(w00, w00, 0x1010);
            b1a[j][1] = __byte_perm(w01, w01, 0x1010);
            b1b[j][0] = __byte_perm(w10, w10, 0x1010);
            b1b[j][1] = __byte_perm(w11, w11, 0x1010);
            b2f[j][0] = __byte_perm(w00, w10, 0x7632);
            b2f[j][1] = __byte_perm(w01, w11, 0x7632);
        }
#pragma unroll
        for (int i = 0; i < 4; i++) {
            int r0 = wm + 16 * i + gid;
            uint32_t u00 = As[sl][r0][tig];
            uint32_t u01 = As[sl][r0][tig + 4];
            uint32_t u02 = As[sl][r0][tig + 8];
            uint32_t u03 = As[sl][r0][tig + 12];
            uint32_t u10 = As[sl][r0 + 8][tig];
            uint32_t u11 = As[sl][r0 + 8][tig + 4];
            uint32_t u12 = As[sl][r0 + 8][tig + 8];
            uint32_t u13 = As[sl][r0 + 8][tig + 12];
            uint32_t a1a[4] = {u00, u10, u01, u11};
            uint32_t a1b[4] = {u02, u12, u03, u13};
            uint32_t a2[4] = {__byte_perm(u00, u02, 0x5410), __byte_perm(u10, u12, 0x5410),
                              __byte_perm(u01, u03, 0x5410), __byte_perm(u11, u13, 0x5410)};
#pragma unroll
            for (int j = 0; j < 4; j++) {
                mma_bf16(acc[i][j], a1a, b1a[j]);
                mma_bf16(acc[i][j], a1b, b1b[j]);
                mma_bf16(acc[i][j], a2, b2f[j]);
            }
        }
        __syncthreads();
    }

#pragma unroll
    for (int i = 0; i < 4; i++) {
#pragma unroll
        for (int j = 0; j < 4; j++) {
            int r0 = bm + wm + 16 * i + gid;
            int r1 = r0 + 8;
            int c = bn + wn + 8 * j + 2 * tig;
            float2 v0 = make_float2(acc[i][j][0], acc[i][j][1]);
            float2 v1 = make_float2(acc[i][j][2], acc[i][j][3]);
            float bx = 0.f, by = 0.f;
            if (bias) { bx = bias[c]; by = bias[c + 1]; }
            if (r0 < M) {
                size_t idx = (size_t)r0 * N + c;
                if (addv) { v0.x += addv[idx]; v0.y += addv[idx + 1]; }
                v0.x += bx; v0.y += by;
                if (flags & FLAG_RELU) { v0.x = fmaxf(v0.x, 0.f); v0.y = fmaxf(v0.y, 0.f); }
                if (C) *(float2*)(C + idx) = v0;
                if (Cp) { Cp[idx] = pack_split(v0.x); Cp[idx + 1] = pack_split(v0.y); }
            }
            if (r1 < M) {
                size_t idx = (size_t)r1 * N + c;
                if (addv) { v1.x += addv[idx]; v1.y += addv[idx + 1]; }
                v1.x += bx; v1.y += by;
                if (flags & FLAG_RELU) { v1.x = fmaxf(v1.x, 0.f); v1.y = fmaxf(v1.y, 0.f); }
                if (C) *(float2*)(C + idx) = v1;
                if (Cp) { Cp[idx] = pack_split(v1.x); Cp[idx + 1] = pack_split(v1.y); }
            }
        }
    }
}

// final: out[n,0:2] = x1[n,:]@W2[256,2] + b2
__global__ void final_kernel(const float* __restrict__ x1, const float* __restrict__ W2,
                             const float* __restrict__ b2, float* __restrict__ out, int N) {
    int warp = (blockIdx.x * blockDim.x + threadIdx.x) >> 5;
    int lane = threadIdx.x & 31;
    if (warp >= N) return;
    const float* xr = x1 + (size_t)warp * HID;
    float s0 = 0.f, s1 = 0.f;
    for (int k = lane; k < HID; k += 32) {
        float xv = xr[k];
        s0 = fmaf(xv, W2[k * 2 + 0], s0);
        s1 = fmaf(xv, W2[k * 2 + 1], s1);
    }
#pragma unroll
    for (int o = 16; o; o >>= 1) {
        s0 += __shfl_xor_sync(0xffffffffu, s0, o);
        s1 += __shfl_xor_sync(0xffffffffu, s1, o);
    }
    if (lane == 0) {
        out[warp * 2 + 0] = s0 + b2[0];
        out[warp * 2 + 1] = s1 + b2[1];
    }
}

// ---------------- host launcher -------------------------------------------------
static inline void* sym(const void* s) {
    void* p = nullptr;
    cudaGetSymbolAddress(&p, s);
    return p;
}

extern "C" void kernel_launch(void* const* d_in, const int* in_sizes, int n_in,
                              void* d_out, int out_size) {
    const float* x_link = (const float*)d_in[0];
    const float* x_flow = (const float*)d_in[1];
    const float* x_path = (const float*)d_in[2];
    const float* e2p = (const float*)d_in[3];
    const float* Wp_link = (const float*)d_in[4];
    const float* bp_link = (const float*)d_in[5];
    const float* Wp_flow = (const float*)d_in[6];
    const float* bp_flow = (const float*)d_in[7];
    const float* Wp_path = (const float*)d_in[8];
    const float* bp_path = (const float*)d_in[9];
    const float* fc_src1 = (const float*)d_in[10];
    const float* fc_dst1 = (const float*)d_in[11];
    const float* fc_e1 = (const float*)d_in[12];
    const float* attn_l1 = (const float*)d_in[13];
    const float* attn_r1 = (const float*)d_in[14];
    const float* attn_e1 = (const float*)d_in[15];
    const float* res_W1 = (const float*)d_in[16];
    const float* fc_src2 = (const float*)d_in[17];
    const float* fc_dst2 = (const float*)d_in[18];
    const float* attn_l2 = (const float*)d_in[19];
    const float* attn_r2 = (const float*)d_in[20];
    const float* res_W2 = (const float*)d_in[21];
    const float* W1 = (const float*)d_in[22];
    const float* b1 = (const float*)d_in[23];
    const float* W2 = (const float*)d_in[24];
    const float* b2 = (const float*)d_in[25];
    const int* src1 = (const int*)d_in[26];
    const int* dst1 = (const int*)d_in[27];
    const int* src2 = (const int*)d_in[28];
    const int* dst2 = (const int*)d_in[29];
    float* out = (float*)d_out;

    float* z1 = (float*)sym(g_z1);
    float* z2 = (float*)sym(g_z2);
    float* aggm1 = (float*)sym(g_aggm1);
    float* aggm2 = (float*)sym(g_aggm2);
    float* x1g = (float*)sym(g_x1);
    uint32_t* hlinkp = (uint32_t*)sym(g_hlinkp);
    uint32_t* hflowp = (uint32_t*)sym(g_hflowp);
    uint32_t* hp0p = (uint32_t*)sym(g_hp0p);
    uint32_t* hp1p = (uint32_t*)sym(g_hp1p);
    uint32_t* hp2p = (uint32_t*)sym(g_hp2p);
    uint32_t* fc1p = (uint32_t*)sym(g_fc1p);
    uint32_t* fc2p = (uint32_t*)sym(g_fc2p);
    uint32_t* rw1p = (uint32_t*)sym(g_rw1p);
    uint32_t* rw2p = (uint32_t*)sym(g_rw2p);
    uint32_t* w1sp = (uint32_t*)sym(g_w1sp);
    uint32_t* w1bp = (uint32_t*)sym(g_w1bp);
    float* vl1 = (float*)sym(g_vl1);
    float* vr1 = (float*)sym(g_vr1);
    float* vl2 = (float*)sym(g_vl2);
    float* vr2 = (float*)sym(g_vr2);
    float* ce = (float*)sym(g_ce);
    float* el1 = (float*)sym(g_el1);
    float* er1 = (float*)sym(g_er1);
    float* el2 = (float*)sym(g_el2);
    float* er2 = (float*)sym(g_er2);
    float* elog1 = (float*)sym(g_elog1);
    float* elog2 = (float*)sym(g_elog2);
    float* denom1 = (float*)sym(g_denom1);
    float* denom2 = (float*)sym(g_denom2);

    cudaStream_t sB;
    cudaStreamCreateWithFlags(&sB, cudaStreamNonBlocking);
    cudaEvent_t evFork, evEr2, evX1p;
    cudaEventCreateWithFlags(&evFork, cudaEventDisableTiming);
    cudaEventCreateWithFlags(&evEr2, cudaEventDisableTiming);
    cudaEventCreateWithFlags(&evX1p, cudaEventDisableTiming);

    dim3 gz1(HDTOT / 128, (N_LINK + 127) / 128);
    dim3 gz2(HDTOT / 128, (N_FLOW + 127) / 128);
    dim3 gres(HID / 128, (N_PATH + 127) / 128);

    // ---------- shared prologue (main stream) ----------
    attnvec_all_kernel<<<dim3(HID, 5), 128>>>(
        fc_src1, attn_l1, vl1, fc_dst1, attn_r1, vr1,
        fc_src2, attn_l2, vl2, fc_dst2, attn_r2, vr2,
        fc_e1, attn_e1, ce);
    pack_all_kernel<<<(PKT + 255) / 256, 256>>>(fc_src1, fc_src2, res_W1, res_W2, W1,
                                                fc1p, fc2p, rw1p, rw2p, w1sp, w1bp);
    cudaMemsetAsync(denom1, 0, (size_t)N_PATH * NH * sizeof(float));
    cudaMemsetAsync(aggm1, 0, (size_t)N_PATH * HID * sizeof(float));
    cudaMemsetAsync(denom2, 0, (size_t)N_PATH * NH * sizeof(float));
    cudaMemsetAsync(aggm2, 0, (size_t)N_PATH * HID * sizeof(float));

    // ---------- fork: stream B runs the full conv1 chain + decoder partial ----------
    cudaEventRecord(evFork, 0);
    cudaStreamWaitEvent(sB, evFork, 0);

    proj_tiled<8><<<(N_LINK + PROJ_R - 1) / PROJ_R, 256, 0, sB>>>(
        x_link, Wp_link, bp_link, hlinkp, vl1, el1, N_LINK);
    proj_tiled<8><<<(N_PATH + PROJ_R - 1) / PROJ_R, 256, 0, sB>>>(
        x_path, Wp_path, bp_path, hp0p, vr1, er1, N_PATH);
    gemm_db16<<<gz1, 256, 0, sB>>>(hlinkp, nullptr, nullptr, fc1p, z1, nullptr,
                                   N_LINK, HDTOT, 1, nullptr, nullptr, 0);
    edge_softmax_kernel<<<(E1 * NH + 255) / 256, 256, 0, sB>>>(
        src1, dst1, el1, er1, e2p, ce, elog1, denom1, E1, 1);
    aggregate_kernel<<<(E1 + 3) / 4, 256, 0, sB>>>(src1, dst1, elog1, denom1, z1, aggm1, E1);
    // hp1 packed only (fp32 copy eliminated)
    gemm_db16<<<gres, 256, 0, sB>>>(hp0p, nullptr, nullptr, rw1p, nullptr, hp1p,
                                    N_PATH, HID, 1, aggm1, nullptr, FLAG_RELU);
    dotvec_packed_kernel<<<N_PATH, 128, 0, sB>>>(hp1p, vr2, er2, N_PATH);
    cudaEventRecord(evEr2, sB);
    // decoder partial: x1part (into retired aggm1) = hp1 @ W1b — overlaps conv2 on main
    gemm_db16<<<gres, 256, 0, sB>>>(hp1p, nullptr, nullptr, w1bp, aggm1, nullptr,
                                    N_PATH, HID, 1, nullptr, nullptr, 0);
    cudaEventRecord(evX1p, sB);

    // ---------- main stream: flow proj + big z2 GEMM ----------
    proj_tiled<16><<<(N_FLOW + PROJ_R - 1) / PROJ_R, 256>>>(
        x_flow, Wp_flow, bp_flow, hflowp, vl2, el2, N_FLOW);
    gemm_db16<<<gz2, 256>>>(hflowp, nullptr, nullptr, fc2p, z2, nullptr,
                            N_FLOW, HDTOT, 1, nullptr, nullptr, 0);

    // ---------- join for er2, then conv2 ----------
    cudaStreamWaitEvent(0, evEr2, 0);

    edge_softmax_kernel<<<(E2 * NH + 255) / 256, 256>>>(
        src2, dst2, el2, er2, nullptr, ce, elog2, denom2, E2, 0);
    aggregate_kernel<<<(E2 + 3) / 4, 256>>>(src2, dst2, elog2, denom2, z2, aggm2, E2);

    gemm_db16<<<gres, 256>>>(hp1p, nullptr, nullptr, rw2p, nullptr, hp2p,
                             N_PATH, HID, 1, aggm2, nullptr, FLAG_RELU);

    // ---------- decoder: x1 = relu(hp2@(W1a+W1c) + x1part + b1) ----------
    cudaStreamWaitEvent(0, evX1p, 0);
    gemm_db16<<<gres, 256>>>(hp2p, nullptr, nullptr, w1sp, x1g, nullptr,
                             N_PATH, HID, 1, aggm1, b1, FLAG_RELU);

    final_kernel<<<(N_PATH * 32 + 255) / 256, 256>>>(x1g, W2, b2, out, N_PATH);
}